// round 1
// baseline (speedup 1.0000x reference)
#include <cuda_runtime.h>
#include <math.h>

#define BB 16
#define CC 256
#define NN 4096
#define DA 64

// Scratch (allocations are forbidden; __device__ globals are the sanctioned path)
__device__ float g_q[(size_t)BB * NN * DA];   // [b][n][a]   16 MB
__device__ float g_k[(size_t)BB * NN * DA];   // [b][n][a]   16 MB
__device__ float g_v[(size_t)BB * NN * CC];   // [b][n][c]   64 MB

// ---------------------------------------------------------------------------
// Kernel 1: fused QKV projection.  y[r,n] = sum_c Wcat[r][c] * x[b][c][n] + bias
// Grid: (N/64, 3 rowgroups, B). Block 256 thr. Tile: 128 rows x 64 n, K-chunk 64.
// rowgroup 0 = Wq(64)+Wk(64); rowgroup 1 = Wv[0:128]; rowgroup 2 = Wv[128:256].
// ---------------------------------------------------------------------------
__global__ __launch_bounds__(256) void proj_kernel(
    const float* __restrict__ x,
    const float* __restrict__ Wq, const float* __restrict__ bq,
    const float* __restrict__ Wk, const float* __restrict__ bk,
    const float* __restrict__ Wv, const float* __restrict__ bv)
{
    __shared__ float xs[64][64];    // [c][n]
    __shared__ float ws[128][64];   // [r][c]

    const int t  = threadIdx.x;
    const int nt = blockIdx.x;
    const int rg = blockIdx.y;
    const int b  = blockIdx.z;
    const int n0 = nt * 64;
    const int tn = t & 15;      // 16 n-groups of 4
    const int tr = t >> 4;      // 16 row-groups of 8

    float acc[8][4];
#pragma unroll
    for (int q = 0; q < 8; q++)
#pragma unroll
        for (int j = 0; j < 4; j++) acc[q][j] = 0.f;

    for (int c0 = 0; c0 < CC; c0 += 64) {
        __syncthreads();
        // load x chunk [64c x 64n], coalesced float4
#pragma unroll
        for (int f = t; f < 64 * 16; f += 256) {
            int cc = f >> 4, n4 = f & 15;
            *(float4*)&xs[cc][n4 * 4] =
                *(const float4*)&x[((size_t)b * CC + (c0 + cc)) * NN + n0 + n4 * 4];
        }
        // load W chunk [128r x 64c], coalesced float4
#pragma unroll
        for (int f = t; f < 128 * 16; f += 256) {
            int r = f >> 4, c4 = f & 15;
            const float* wp;
            if (rg == 0) wp = (r < 64) ? (Wq + r * CC) : (Wk + (r - 64) * CC);
            else         wp = Wv + ((size_t)((rg - 1) * 128 + r)) * CC;
            *(float4*)&ws[r][c4 * 4] = *(const float4*)&wp[c0 + c4 * 4];
        }
        __syncthreads();
        // compute: per warp W reads are 2-address broadcasts; x reads conflict-free
#pragma unroll 8
        for (int cc = 0; cc < 64; cc++) {
            float4 xv = *(float4*)&xs[cc][tn * 4];
#pragma unroll
            for (int q = 0; q < 8; q++) {
                float wv = ws[tr * 8 + q][cc];
                acc[q][0] = fmaf(wv, xv.x, acc[q][0]);
                acc[q][1] = fmaf(wv, xv.y, acc[q][1]);
                acc[q][2] = fmaf(wv, xv.z, acc[q][2]);
                acc[q][3] = fmaf(wv, xv.w, acc[q][3]);
            }
        }
    }

    // store (+bias) into [b][n][row] layouts (scattered; acceptable at round 0)
#pragma unroll
    for (int q = 0; q < 8; q++) {
        int r = tr * 8 + q;
        if (rg == 0) {
            if (r < 64) {
                float bias = bq[r];
                float* dst = g_q + (size_t)b * NN * DA;
#pragma unroll
                for (int j = 0; j < 4; j++) {
                    int n = n0 + tn * 4 + j;
                    dst[(size_t)n * DA + r] = acc[q][j] + bias;
                }
            } else {
                float bias = bk[r - 64];
                float* dst = g_k + (size_t)b * NN * DA;
#pragma unroll
                for (int j = 0; j < 4; j++) {
                    int n = n0 + tn * 4 + j;
                    dst[(size_t)n * DA + (r - 64)] = acc[q][j] + bias;
                }
            }
        } else {
            int c = (rg - 1) * 128 + r;
            float bias = bv[c];
            float* dst = g_v + (size_t)b * NN * CC;
#pragma unroll
            for (int j = 0; j < 4; j++) {
                int n = n0 + tn * 4 + j;
                dst[(size_t)n * CC + c] = acc[q][j] + bias;
            }
        }
    }
}

// ---------------------------------------------------------------------------
// Kernel 2: flash attention + residual.
// Grid: (N/64 i-tiles, B). Block 256 thr, 1 CTA/SM (smem ~118 KB).
// Per j-tile (64): S = q k^T / 64 -> online softmax -> acc = acc*corr + P V.
// acc lives in registers: 4 i x 16 c per thread.
// ---------------------------------------------------------------------------
#define QSTR 68   // pad: q/k row loads conflict-free
#define PSTR 65   // pad: P loads in PV become 2-address broadcasts

__global__ __launch_bounds__(256) void attn_kernel(
    const float* __restrict__ x, float* __restrict__ out)
{
    extern __shared__ float smem[];
    float* qs     = smem;                  // 64*68
    float* ks     = qs + 64 * QSTR;        // 64*68
    float* vs     = ks + 64 * QSTR;        // 64*256
    float* Ps     = vs + 64 * 256;         // 64*65
    float* corr_s = Ps + 64 * PSTR;        // 64
    float* l_s    = corr_s + 64;           // 64
    float* m_s    = l_s + 64;              // 64

    const int t  = threadIdx.x;
    const int b  = blockIdx.y;
    const int i0 = blockIdx.x * 64;

    // S-phase mapping: 4 threads per row i, each covers 16 j (j = jj*4 + sjg)
    const int si  = t >> 2;
    const int sjg = t & 3;
    // PV-phase mapping: thread covers i = pti*4..+3, c = pci*16..+15
    const int pci = t & 15;
    const int pti = t >> 4;

    // load q tile
    {
        const float* qg = g_q + ((size_t)b * NN + i0) * DA;
#pragma unroll
        for (int f = t; f < 64 * 16; f += 256) {
            int ii = f >> 4, a4 = f & 15;
            *(float4*)&qs[ii * QSTR + a4 * 4] = *(const float4*)&qg[ii * DA + a4 * 4];
        }
    }
    if (t < 64) { l_s[t] = 0.f; m_s[t] = -1e30f; }

    float acc[4][16];
#pragma unroll
    for (int r = 0; r < 4; r++)
#pragma unroll
        for (int cc = 0; cc < 16; cc++) acc[r][cc] = 0.f;

    const float scale = 1.0f / 64.0f;   // 1/sqrt(N)

    for (int j0 = 0; j0 < NN; j0 += 64) {
        __syncthreads();   // previous PV done before overwriting ks/vs/Ps
        // load k tile [64j x 64a]
        {
            const float* kg = g_k + ((size_t)b * NN + j0) * DA;
#pragma unroll
            for (int f = t; f < 64 * 16; f += 256) {
                int jj = f >> 4, a4 = f & 15;
                *(float4*)&ks[jj * QSTR + a4 * 4] = *(const float4*)&kg[jj * DA + a4 * 4];
            }
        }
        // load v tile [64j x 256c]
        {
            const float* vg = g_v + ((size_t)b * NN + j0) * CC;
#pragma unroll
            for (int f = t; f < 64 * 64; f += 256) {
                int jj = f >> 6, c4 = f & 63;
                *(float4*)&vs[jj * 256 + c4 * 4] = *(const float4*)&vg[jj * CC + c4 * 4];
            }
        }
        __syncthreads();

        // ---- S = q . k ----
        float s[16];
#pragma unroll
        for (int jj = 0; jj < 16; jj++) s[jj] = 0.f;
#pragma unroll
        for (int a4 = 0; a4 < 16; a4++) {
            float4 q4 = *(float4*)&qs[si * QSTR + a4 * 4];
#pragma unroll
            for (int jj = 0; jj < 16; jj++) {
                int j = (jj << 2) | sjg;
                float4 k4 = *(float4*)&ks[j * QSTR + a4 * 4];
                s[jj] += q4.x * k4.x + q4.y * k4.y + q4.z * k4.z + q4.w * k4.w;
            }
        }

        // ---- online softmax ----
        float rm = -1e30f;
#pragma unroll
        for (int jj = 0; jj < 16; jj++) { s[jj] *= scale; rm = fmaxf(rm, s[jj]); }
        rm = fmaxf(rm, __shfl_xor_sync(0xffffffffu, rm, 1));
        rm = fmaxf(rm, __shfl_xor_sync(0xffffffffu, rm, 2));
        float mold = m_s[si];
        float mnew = fmaxf(mold, rm);
        float rs = 0.f;
#pragma unroll
        for (int jj = 0; jj < 16; jj++) {
            float p = __expf(s[jj] - mnew);
            Ps[si * PSTR + ((jj << 2) | sjg)] = p;
            rs += p;
        }
        rs += __shfl_xor_sync(0xffffffffu, rs, 1);
        rs += __shfl_xor_sync(0xffffffffu, rs, 2);
        float cr = __expf(mold - mnew);
        if (sjg == 0) {
            m_s[si]    = mnew;
            l_s[si]    = l_s[si] * cr + rs;
            corr_s[si] = cr;
        }
        __syncthreads();

        // ---- acc = acc*corr + P V ----
#pragma unroll
        for (int r = 0; r < 4; r++) {
            float c = corr_s[pti * 4 + r];
#pragma unroll
            for (int cc = 0; cc < 16; cc++) acc[r][cc] *= c;
        }
        const float* Prow0 = Ps + (pti * 4 + 0) * PSTR;
        const float* Prow1 = Ps + (pti * 4 + 1) * PSTR;
        const float* Prow2 = Ps + (pti * 4 + 2) * PSTR;
        const float* Prow3 = Ps + (pti * 4 + 3) * PSTR;
        const float* vrow  = vs + pci * 16;
#pragma unroll 8
        for (int j = 0; j < 64; j++) {
            float p0 = Prow0[j], p1 = Prow1[j], p2 = Prow2[j], p3 = Prow3[j];
            float4 v0 = *(const float4*)&vrow[j * 256 + 0];
            float4 v1 = *(const float4*)&vrow[j * 256 + 4];
            float4 v2 = *(const float4*)&vrow[j * 256 + 8];
            float4 v3 = *(const float4*)&vrow[j * 256 + 12];
            acc[0][0]  = fmaf(p0, v0.x, acc[0][0]);  acc[0][1]  = fmaf(p0, v0.y, acc[0][1]);
            acc[0][2]  = fmaf(p0, v0.z, acc[0][2]);  acc[0][3]  = fmaf(p0, v0.w, acc[0][3]);
            acc[0][4]  = fmaf(p0, v1.x, acc[0][4]);  acc[0][5]  = fmaf(p0, v1.y, acc[0][5]);
            acc[0][6]  = fmaf(p0, v1.z, acc[0][6]);  acc[0][7]  = fmaf(p0, v1.w, acc[0][7]);
            acc[0][8]  = fmaf(p0, v2.x, acc[0][8]);  acc[0][9]  = fmaf(p0, v2.y, acc[0][9]);
            acc[0][10] = fmaf(p0, v2.z, acc[0][10]); acc[0][11] = fmaf(p0, v2.w, acc[0][11]);
            acc[0][12] = fmaf(p0, v3.x, acc[0][12]); acc[0][13] = fmaf(p0, v3.y, acc[0][13]);
            acc[0][14] = fmaf(p0, v3.z, acc[0][14]); acc[0][15] = fmaf(p0, v3.w, acc[0][15]);

            acc[1][0]  = fmaf(p1, v0.x, acc[1][0]);  acc[1][1]  = fmaf(p1, v0.y, acc[1][1]);
            acc[1][2]  = fmaf(p1, v0.z, acc[1][2]);  acc[1][3]  = fmaf(p1, v0.w, acc[1][3]);
            acc[1][4]  = fmaf(p1, v1.x, acc[1][4]);  acc[1][5]  = fmaf(p1, v1.y, acc[1][5]);
            acc[1][6]  = fmaf(p1, v1.z, acc[1][6]);  acc[1][7]  = fmaf(p1, v1.w, acc[1][7]);
            acc[1][8]  = fmaf(p1, v2.x, acc[1][8]);  acc[1][9]  = fmaf(p1, v2.y, acc[1][9]);
            acc[1][10] = fmaf(p1, v2.z, acc[1][10]); acc[1][11] = fmaf(p1, v2.w, acc[1][11]);
            acc[1][12] = fmaf(p1, v3.x, acc[1][12]); acc[1][13] = fmaf(p1, v3.y, acc[1][13]);
            acc[1][14] = fmaf(p1, v3.z, acc[1][14]); acc[1][15] = fmaf(p1, v3.w, acc[1][15]);

            acc[2][0]  = fmaf(p2, v0.x, acc[2][0]);  acc[2][1]  = fmaf(p2, v0.y, acc[2][1]);
            acc[2][2]  = fmaf(p2, v0.z, acc[2][2]);  acc[2][3]  = fmaf(p2, v0.w, acc[2][3]);
            acc[2][4]  = fmaf(p2, v1.x, acc[2][4]);  acc[2][5]  = fmaf(p2, v1.y, acc[2][5]);
            acc[2][6]  = fmaf(p2, v1.z, acc[2][6]);  acc[2][7]  = fmaf(p2, v1.w, acc[2][7]);
            acc[2][8]  = fmaf(p2, v2.x, acc[2][8]);  acc[2][9]  = fmaf(p2, v2.y, acc[2][9]);
            acc[2][10] = fmaf(p2, v2.z, acc[2][10]); acc[2][11] = fmaf(p2, v2.w, acc[2][11]);
            acc[2][12] = fmaf(p2, v3.x, acc[2][12]); acc[2][13] = fmaf(p2, v3.y, acc[2][13]);
            acc[2][14] = fmaf(p2, v3.z, acc[2][14]); acc[2][15] = fmaf(p2, v3.w, acc[2][15]);

            acc[3][0]  = fmaf(p3, v0.x, acc[3][0]);  acc[3][1]  = fmaf(p3, v0.y, acc[3][1]);
            acc[3][2]  = fmaf(p3, v0.z, acc[3][2]);  acc[3][3]  = fmaf(p3, v0.w, acc[3][3]);
            acc[3][4]  = fmaf(p3, v1.x, acc[3][4]);  acc[3][5]  = fmaf(p3, v1.y, acc[3][5]);
            acc[3][6]  = fmaf(p3, v1.z, acc[3][6]);  acc[3][7]  = fmaf(p3, v1.w, acc[3][7]);
            acc[3][8]  = fmaf(p3, v2.x, acc[3][8]);  acc[3][9]  = fmaf(p3, v2.y, acc[3][9]);
            acc[3][10] = fmaf(p3, v2.z, acc[3][10]); acc[3][11] = fmaf(p3, v2.w, acc[3][11]);
            acc[3][12] = fmaf(p3, v3.x, acc[3][12]); acc[3][13] = fmaf(p3, v3.y, acc[3][13]);
            acc[3][14] = fmaf(p3, v3.z, acc[3][14]); acc[3][15] = fmaf(p3, v3.w, acc[3][15]);
        }
    }

    // ---- epilogue: out[b][c][i] = acc/l + x ----
    float linv[4];
#pragma unroll
    for (int r = 0; r < 4; r++) linv[r] = 1.0f / l_s[pti * 4 + r];

#pragma unroll
    for (int cc = 0; cc < 16; cc++) {
        int c = pci * 16 + cc;
        size_t base = ((size_t)b * CC + c) * NN + i0 + pti * 4;
        float4 xv = *(const float4*)&x[base];
        float4 o;
        o.x = fmaf(acc[0][cc], linv[0], xv.x);
        o.y = fmaf(acc[1][cc], linv[1], xv.y);
        o.z = fmaf(acc[2][cc], linv[2], xv.z);
        o.w = fmaf(acc[3][cc], linv[3], xv.w);
        *(float4*)&out[base] = o;
    }
}

// ---------------------------------------------------------------------------
extern "C" void kernel_launch(void* const* d_in, const int* in_sizes, int n_in,
                              void* d_out, int out_size)
{
    const float* x  = (const float*)d_in[0];
    const float* Wq = (const float*)d_in[1];
    const float* bq = (const float*)d_in[2];
    const float* Wk = (const float*)d_in[3];
    const float* bk = (const float*)d_in[4];
    const float* Wv = (const float*)d_in[5];
    const float* bv = (const float*)d_in[6];
    float* out = (float*)d_out;

    const int smem_bytes = (64 * QSTR + 64 * QSTR + 64 * 256 + 64 * PSTR + 3 * 64) * 4;
    cudaFuncSetAttribute(attn_kernel, cudaFuncAttributeMaxDynamicSharedMemorySize, smem_bytes);

    proj_kernel<<<dim3(64, 3, BB), 256>>>(x, Wq, bq, Wk, bk, Wv, bv);
    attn_kernel<<<dim3(64, BB), 256, smem_bytes>>>(x, out);
}

// round 2
// speedup vs baseline: 1.8705x; 1.8705x over previous
#include <cuda_runtime.h>
#include <math.h>

#define BB 16
#define CC 256
#define NN 4096
#define DA 64

// Scratch (allocations are forbidden; __device__ globals are the sanctioned path)
__device__ float g_q[(size_t)BB * NN * DA];   // [b][n][a]   16 MB
__device__ float g_k[(size_t)BB * NN * DA];   // [b][n][a]   16 MB
__device__ float g_v[(size_t)BB * NN * CC];   // [b][n][c]   64 MB

// ---------------------------------------------------------------------------
// Kernel 1: fused QKV projection.  y[r,n] = sum_c Wcat[r][c] * x[b][c][n] + bias
// ---------------------------------------------------------------------------
__global__ __launch_bounds__(256) void proj_kernel(
    const float* __restrict__ x,
    const float* __restrict__ Wq, const float* __restrict__ bq,
    const float* __restrict__ Wk, const float* __restrict__ bk,
    const float* __restrict__ Wv, const float* __restrict__ bv)
{
    __shared__ float xs[64][64];    // [c][n]
    __shared__ float ws[128][64];   // [r][c]

    const int t  = threadIdx.x;
    const int nt = blockIdx.x;
    const int rg = blockIdx.y;
    const int b  = blockIdx.z;
    const int n0 = nt * 64;
    const int tn = t & 15;      // 16 n-groups of 4
    const int tr = t >> 4;      // 16 row-groups of 8

    float acc[8][4];
#pragma unroll
    for (int q = 0; q < 8; q++)
#pragma unroll
        for (int j = 0; j < 4; j++) acc[q][j] = 0.f;

    for (int c0 = 0; c0 < CC; c0 += 64) {
        __syncthreads();
#pragma unroll
        for (int f = t; f < 64 * 16; f += 256) {
            int cc = f >> 4, n4 = f & 15;
            *(float4*)&xs[cc][n4 * 4] =
                *(const float4*)&x[((size_t)b * CC + (c0 + cc)) * NN + n0 + n4 * 4];
        }
#pragma unroll
        for (int f = t; f < 128 * 16; f += 256) {
            int r = f >> 4, c4 = f & 15;
            const float* wp;
            if (rg == 0) wp = (r < 64) ? (Wq + r * CC) : (Wk + (r - 64) * CC);
            else         wp = Wv + ((size_t)((rg - 1) * 128 + r)) * CC;
            *(float4*)&ws[r][c4 * 4] = *(const float4*)&wp[c0 + c4 * 4];
        }
        __syncthreads();
#pragma unroll 8
        for (int cc = 0; cc < 64; cc++) {
            float4 xv = *(float4*)&xs[cc][tn * 4];
#pragma unroll
            for (int q = 0; q < 8; q++) {
                float wv = ws[tr * 8 + q][cc];
                acc[q][0] = fmaf(wv, xv.x, acc[q][0]);
                acc[q][1] = fmaf(wv, xv.y, acc[q][1]);
                acc[q][2] = fmaf(wv, xv.z, acc[q][2]);
                acc[q][3] = fmaf(wv, xv.w, acc[q][3]);
            }
        }
    }

#pragma unroll
    for (int q = 0; q < 8; q++) {
        int r = tr * 8 + q;
        if (rg == 0) {
            if (r < 64) {
                float bias = bq[r];
                float* dst = g_q + (size_t)b * NN * DA;
#pragma unroll
                for (int j = 0; j < 4; j++) {
                    int n = n0 + tn * 4 + j;
                    dst[(size_t)n * DA + r] = acc[q][j] + bias;
                }
            } else {
                float bias = bk[r - 64];
                float* dst = g_k + (size_t)b * NN * DA;
#pragma unroll
                for (int j = 0; j < 4; j++) {
                    int n = n0 + tn * 4 + j;
                    dst[(size_t)n * DA + (r - 64)] = acc[q][j] + bias;
                }
            }
        } else {
            int c = (rg - 1) * 128 + r;
            float bias = bv[c];
            float* dst = g_v + (size_t)b * NN * CC;
#pragma unroll
            for (int j = 0; j < 4; j++) {
                int n = n0 + tn * 4 + j;
                dst[(size_t)n * CC + c] = acc[q][j] + bias;
            }
        }
    }
}

// ---------------------------------------------------------------------------
// Kernel 2: flash attention + residual.
// Grid: (N/64 i-tiles, B). Block 256 thr, 1 CTA/SM.
// PV column mapping: thread covers c = g*64 + pci*4 + u  (g=0..3, u=0..3)
// so lanes 0..15 read CONTIGUOUS float4s from vs (conflict-free; lanes 16..31
// broadcast-duplicate). This removes the 8-way V bank conflicts of round 1.
// ---------------------------------------------------------------------------
#define QSTR 68   // pad: q/k row loads conflict-free
#define PSTR 65   // pad: P loads broadcast cleanly

__global__ __launch_bounds__(256) void attn_kernel(
    const float* __restrict__ x, float* __restrict__ out)
{
    extern __shared__ float smem[];
    float* qs     = smem;                  // 64*68
    float* ks     = qs + 64 * QSTR;        // 64*68
    float* vs     = ks + 64 * QSTR;        // 64*256
    float* Ps     = vs + 64 * 256;         // 64*65
    float* corr_s = Ps + 64 * PSTR;        // 64
    float* l_s    = corr_s + 64;           // 64
    float* m_s    = l_s + 64;              // 64

    const int t  = threadIdx.x;
    const int b  = blockIdx.y;
    const int i0 = blockIdx.x * 64;

    // S-phase mapping: 4 threads per row i, each covers 16 j (j = jj*4 + sjg)
    const int si  = t >> 2;
    const int sjg = t & 3;
    // PV-phase mapping: thread covers i = pti*4..+3, c = g*64 + pci*4 + u
    const int pci = t & 15;
    const int pti = t >> 4;

    // load q tile
    {
        const float* qg = g_q + ((size_t)b * NN + i0) * DA;
#pragma unroll
        for (int f = t; f < 64 * 16; f += 256) {
            int ii = f >> 4, a4 = f & 15;
            *(float4*)&qs[ii * QSTR + a4 * 4] = *(const float4*)&qg[ii * DA + a4 * 4];
        }
    }
    if (t < 64) { l_s[t] = 0.f; m_s[t] = -1e30f; }

    float acc[4][16];
#pragma unroll
    for (int r = 0; r < 4; r++)
#pragma unroll
        for (int cc = 0; cc < 16; cc++) acc[r][cc] = 0.f;

    const float scale = 1.0f / 64.0f;   // 1/sqrt(N)

    for (int j0 = 0; j0 < NN; j0 += 64) {
        __syncthreads();   // previous PV done before overwriting ks/vs/Ps
        // load k tile [64j x 64a]
        {
            const float* kg = g_k + ((size_t)b * NN + j0) * DA;
#pragma unroll
            for (int f = t; f < 64 * 16; f += 256) {
                int jj = f >> 4, a4 = f & 15;
                *(float4*)&ks[jj * QSTR + a4 * 4] = *(const float4*)&kg[jj * DA + a4 * 4];
            }
        }
        // load v tile [64j x 256c]
        {
            const float* vg = g_v + ((size_t)b * NN + j0) * CC;
#pragma unroll
            for (int f = t; f < 64 * 64; f += 256) {
                int jj = f >> 6, c4 = f & 63;
                *(float4*)&vs[jj * 256 + c4 * 4] = *(const float4*)&vg[jj * CC + c4 * 4];
            }
        }
        __syncthreads();

        // ---- S = q . k ---- (pure FFMA chains)
        float s[16];
#pragma unroll
        for (int jj = 0; jj < 16; jj++) s[jj] = 0.f;
#pragma unroll
        for (int a4 = 0; a4 < 16; a4++) {
            float4 q4 = *(float4*)&qs[si * QSTR + a4 * 4];
#pragma unroll
            for (int jj = 0; jj < 16; jj++) {
                int j = (jj << 2) | sjg;
                float4 k4 = *(float4*)&ks[j * QSTR + a4 * 4];
                s[jj] = fmaf(q4.x, k4.x, s[jj]);
                s[jj] = fmaf(q4.y, k4.y, s[jj]);
                s[jj] = fmaf(q4.z, k4.z, s[jj]);
                s[jj] = fmaf(q4.w, k4.w, s[jj]);
            }
        }

        // ---- online softmax ----
        float rm = -1e30f;
#pragma unroll
        for (int jj = 0; jj < 16; jj++) { s[jj] *= scale; rm = fmaxf(rm, s[jj]); }
        rm = fmaxf(rm, __shfl_xor_sync(0xffffffffu, rm, 1));
        rm = fmaxf(rm, __shfl_xor_sync(0xffffffffu, rm, 2));
        float mold = m_s[si];
        float mnew = fmaxf(mold, rm);
        float rs = 0.f;
#pragma unroll
        for (int jj = 0; jj < 16; jj++) {
            float p = __expf(s[jj] - mnew);
            Ps[si * PSTR + ((jj << 2) | sjg)] = p;
            rs += p;
        }
        rs += __shfl_xor_sync(0xffffffffu, rs, 1);
        rs += __shfl_xor_sync(0xffffffffu, rs, 2);
        float cr = __expf(mold - mnew);
        if (sjg == 0) {
            m_s[si]    = mnew;
            l_s[si]    = l_s[si] * cr + rs;
            corr_s[si] = cr;
        }
        __syncthreads();

        // ---- acc = acc*corr + P V ----
#pragma unroll
        for (int r = 0; r < 4; r++) {
            float c = corr_s[pti * 4 + r];
#pragma unroll
            for (int cc = 0; cc < 16; cc++) acc[r][cc] *= c;
        }
        const float* Prow0 = Ps + (pti * 4 + 0) * PSTR;
        const float* Prow1 = Ps + (pti * 4 + 1) * PSTR;
        const float* Prow2 = Ps + (pti * 4 + 2) * PSTR;
        const float* Prow3 = Ps + (pti * 4 + 3) * PSTR;
        const int vcol = pci * 4;   // contiguous float4 across lanes 0..15
#pragma unroll 4
        for (int j = 0; j < 64; j++) {
            float p0 = Prow0[j], p1 = Prow1[j], p2 = Prow2[j], p3 = Prow3[j];
            const float* vr = vs + j * 256 + vcol;
            float4 v0 = *(const float4*)&vr[0];     // c = 0*64 + pci*4
            float4 v1 = *(const float4*)&vr[64];    // c = 1*64 + pci*4
            float4 v2 = *(const float4*)&vr[128];   // c = 2*64 + pci*4
            float4 v3 = *(const float4*)&vr[192];   // c = 3*64 + pci*4
            acc[0][0]  = fmaf(p0, v0.x, acc[0][0]);  acc[0][1]  = fmaf(p0, v0.y, acc[0][1]);
            acc[0][2]  = fmaf(p0, v0.z, acc[0][2]);  acc[0][3]  = fmaf(p0, v0.w, acc[0][3]);
            acc[0][4]  = fmaf(p0, v1.x, acc[0][4]);  acc[0][5]  = fmaf(p0, v1.y, acc[0][5]);
            acc[0][6]  = fmaf(p0, v1.z, acc[0][6]);  acc[0][7]  = fmaf(p0, v1.w, acc[0][7]);
            acc[0][8]  = fmaf(p0, v2.x, acc[0][8]);  acc[0][9]  = fmaf(p0, v2.y, acc[0][9]);
            acc[0][10] = fmaf(p0, v2.z, acc[0][10]); acc[0][11] = fmaf(p0, v2.w, acc[0][11]);
            acc[0][12] = fmaf(p0, v3.x, acc[0][12]); acc[0][13] = fmaf(p0, v3.y, acc[0][13]);
            acc[0][14] = fmaf(p0, v3.z, acc[0][14]); acc[0][15] = fmaf(p0, v3.w, acc[0][15]);

            acc[1][0]  = fmaf(p1, v0.x, acc[1][0]);  acc[1][1]  = fmaf(p1, v0.y, acc[1][1]);
            acc[1][2]  = fmaf(p1, v0.z, acc[1][2]);  acc[1][3]  = fmaf(p1, v0.w, acc[1][3]);
            acc[1][4]  = fmaf(p1, v1.x, acc[1][4]);  acc[1][5]  = fmaf(p1, v1.y, acc[1][5]);
            acc[1][6]  = fmaf(p1, v1.z, acc[1][6]);  acc[1][7]  = fmaf(p1, v1.w, acc[1][7]);
            acc[1][8]  = fmaf(p1, v2.x, acc[1][8]);  acc[1][9]  = fmaf(p1, v2.y, acc[1][9]);
            acc[1][10] = fmaf(p1, v2.z, acc[1][10]); acc[1][11] = fmaf(p1, v2.w, acc[1][11]);
            acc[1][12] = fmaf(p1, v3.x, acc[1][12]); acc[1][13] = fmaf(p1, v3.y, acc[1][13]);
            acc[1][14] = fmaf(p1, v3.z, acc[1][14]); acc[1][15] = fmaf(p1, v3.w, acc[1][15]);

            acc[2][0]  = fmaf(p2, v0.x, acc[2][0]);  acc[2][1]  = fmaf(p2, v0.y, acc[2][1]);
            acc[2][2]  = fmaf(p2, v0.z, acc[2][2]);  acc[2][3]  = fmaf(p2, v0.w, acc[2][3]);
            acc[2][4]  = fmaf(p2, v1.x, acc[2][4]);  acc[2][5]  = fmaf(p2, v1.y, acc[2][5]);
            acc[2][6]  = fmaf(p2, v1.z, acc[2][6]);  acc[2][7]  = fmaf(p2, v1.w, acc[2][7]);
            acc[2][8]  = fmaf(p2, v2.x, acc[2][8]);  acc[2][9]  = fmaf(p2, v2.y, acc[2][9]);
            acc[2][10] = fmaf(p2, v2.z, acc[2][10]); acc[2][11] = fmaf(p2, v2.w, acc[2][11]);
            acc[2][12] = fmaf(p2, v3.x, acc[2][12]); acc[2][13] = fmaf(p2, v3.y, acc[2][13]);
            acc[2][14] = fmaf(p2, v3.z, acc[2][14]); acc[2][15] = fmaf(p2, v3.w, acc[2][15]);

            acc[3][0]  = fmaf(p3, v0.x, acc[3][0]);  acc[3][1]  = fmaf(p3, v0.y, acc[3][1]);
            acc[3][2]  = fmaf(p3, v0.z, acc[3][2]);  acc[3][3]  = fmaf(p3, v0.w, acc[3][3]);
            acc[3][4]  = fmaf(p3, v1.x, acc[3][4]);  acc[3][5]  = fmaf(p3, v1.y, acc[3][5]);
            acc[3][6]  = fmaf(p3, v1.z, acc[3][6]);  acc[3][7]  = fmaf(p3, v1.w, acc[3][7]);
            acc[3][8]  = fmaf(p3, v2.x, acc[3][8]);  acc[3][9]  = fmaf(p3, v2.y, acc[3][9]);
            acc[3][10] = fmaf(p3, v2.z, acc[3][10]); acc[3][11] = fmaf(p3, v2.w, acc[3][11]);
            acc[3][12] = fmaf(p3, v3.x, acc[3][12]); acc[3][13] = fmaf(p3, v3.y, acc[3][13]);
            acc[3][14] = fmaf(p3, v3.z, acc[3][14]); acc[3][15] = fmaf(p3, v3.w, acc[3][15]);
        }
    }

    // ---- epilogue: out[b][c][i] = acc/l + x ----
    float linv[4];
#pragma unroll
    for (int r = 0; r < 4; r++) linv[r] = 1.0f / l_s[pti * 4 + r];

#pragma unroll
    for (int g = 0; g < 4; g++) {
#pragma unroll
        for (int u = 0; u < 4; u++) {
            int cc = g * 4 + u;
            int c  = g * 64 + pci * 4 + u;
            size_t base = ((size_t)b * CC + c) * NN + i0 + pti * 4;
            float4 xv = *(const float4*)&x[base];
            float4 o;
            o.x = fmaf(acc[0][cc], linv[0], xv.x);
            o.y = fmaf(acc[1][cc], linv[1], xv.y);
            o.z = fmaf(acc[2][cc], linv[2], xv.z);
            o.w = fmaf(acc[3][cc], linv[3], xv.w);
            *(float4*)&out[base] = o;
        }
    }
}

// ---------------------------------------------------------------------------
extern "C" void kernel_launch(void* const* d_in, const int* in_sizes, int n_in,
                              void* d_out, int out_size)
{
    const float* x  = (const float*)d_in[0];
    const float* Wq = (const float*)d_in[1];
    const float* bq = (const float*)d_in[2];
    const float* Wk = (const float*)d_in[3];
    const float* bk = (const float*)d_in[4];
    const float* Wv = (const float*)d_in[5];
    const float* bv = (const float*)d_in[6];
    float* out = (float*)d_out;

    const int smem_bytes = (64 * QSTR + 64 * QSTR + 64 * 256 + 64 * PSTR + 3 * 64) * 4;
    cudaFuncSetAttribute(attn_kernel, cudaFuncAttributeMaxDynamicSharedMemorySize, smem_bytes);

    proj_kernel<<<dim3(64, 3, BB), 256>>>(x, Wq, bq, Wk, bk, Wv, bv);
    attn_kernel<<<dim3(64, BB), 256, smem_bytes>>>(x, out);
}

// round 3
// speedup vs baseline: 1.8941x; 1.0126x over previous
#include <cuda_runtime.h>
#include <math.h>

#define BB 16
#define CC 256
#define NN 4096
#define DA 64

typedef unsigned long long u64;

// packed fp32x2 ops (sm_103a; ptxas never emits these from C++)
#define F2FMA(d, a, b, c) asm("fma.rn.f32x2 %0, %1, %2, %3;" : "=l"(d) : "l"(a), "l"(b), "l"(c))
#define F2MUL(d, a, b)    asm("mul.rn.f32x2 %0, %1, %2;"     : "=l"(d) : "l"(a), "l"(b))
#define F2BCAST(d, s)     asm("mov.b64 %0, {%1, %1};" : "=l"(d) : "r"(__float_as_uint(s)))
#define F2UNPACK(lo, hi, v) asm("mov.b64 {%0, %1}, %2;" : "=f"(lo), "=f"(hi) : "l"(v))

// Scratch (allocations are forbidden; __device__ globals are the sanctioned path)
__device__ float g_q[(size_t)BB * NN * DA];   // [b][n][a]   16 MB  (pre-scaled by 1/64)
__device__ float g_k[(size_t)BB * NN * DA];   // [b][n][a]   16 MB
__device__ float g_v[(size_t)BB * NN * CC];   // [b][n][c]   64 MB

// ---------------------------------------------------------------------------
// Kernel 1: fused QKV projection (FFMA2 inner loop).
// ---------------------------------------------------------------------------
__global__ __launch_bounds__(256) void proj_kernel(
    const float* __restrict__ x,
    const float* __restrict__ Wq, const float* __restrict__ bq,
    const float* __restrict__ Wk, const float* __restrict__ bk,
    const float* __restrict__ Wv, const float* __restrict__ bv)
{
    __shared__ float xs[64][64];    // [c][n]
    __shared__ float ws[128][64];   // [r][c]

    const int t  = threadIdx.x;
    const int nt = blockIdx.x;
    const int rg = blockIdx.y;
    const int b  = blockIdx.z;
    const int n0 = nt * 64;
    const int tn = t & 15;      // 16 n-groups of 4
    const int tr = t >> 4;      // 16 row-groups of 8

    u64 accp[8][2];
#pragma unroll
    for (int q = 0; q < 8; q++) { accp[q][0] = 0ull; accp[q][1] = 0ull; }

    for (int c0 = 0; c0 < CC; c0 += 64) {
        __syncthreads();
#pragma unroll
        for (int f = t; f < 64 * 16; f += 256) {
            int cc = f >> 4, n4 = f & 15;
            *(float4*)&xs[cc][n4 * 4] =
                *(const float4*)&x[((size_t)b * CC + (c0 + cc)) * NN + n0 + n4 * 4];
        }
#pragma unroll
        for (int f = t; f < 128 * 16; f += 256) {
            int r = f >> 4, c4 = f & 15;
            const float* wp;
            if (rg == 0) wp = (r < 64) ? (Wq + r * CC) : (Wk + (r - 64) * CC);
            else         wp = Wv + ((size_t)((rg - 1) * 128 + r)) * CC;
            *(float4*)&ws[r][c4 * 4] = *(const float4*)&wp[c0 + c4 * 4];
        }
        __syncthreads();
#pragma unroll 8
        for (int cc = 0; cc < 64; cc++) {
            ulonglong2 xp = *(ulonglong2*)&xs[cc][tn * 4];
#pragma unroll
            for (int q = 0; q < 8; q++) {
                u64 wpk; F2BCAST(wpk, ws[tr * 8 + q][cc]);
                F2FMA(accp[q][0], wpk, xp.x, accp[q][0]);
                F2FMA(accp[q][1], wpk, xp.y, accp[q][1]);
            }
        }
    }

    float acc[8][4];
#pragma unroll
    for (int q = 0; q < 8; q++) {
        F2UNPACK(acc[q][0], acc[q][1], accp[q][0]);
        F2UNPACK(acc[q][2], acc[q][3], accp[q][1]);
    }

    const float qscale = 1.0f / 64.0f;   // fold 1/sqrt(N) into q
#pragma unroll
    for (int q = 0; q < 8; q++) {
        int r = tr * 8 + q;
        if (rg == 0) {
            if (r < 64) {
                float bias = bq[r];
                float* dst = g_q + (size_t)b * NN * DA;
#pragma unroll
                for (int j = 0; j < 4; j++) {
                    int n = n0 + tn * 4 + j;
                    dst[(size_t)n * DA + r] = (acc[q][j] + bias) * qscale;
                }
            } else {
                float bias = bk[r - 64];
                float* dst = g_k + (size_t)b * NN * DA;
#pragma unroll
                for (int j = 0; j < 4; j++) {
                    int n = n0 + tn * 4 + j;
                    dst[(size_t)n * DA + (r - 64)] = acc[q][j] + bias;
                }
            }
        } else {
            int c = (rg - 1) * 128 + r;
            float bias = bv[c];
            float* dst = g_v + (size_t)b * NN * CC;
#pragma unroll
            for (int j = 0; j < 4; j++) {
                int n = n0 + tn * 4 + j;
                dst[(size_t)n * CC + c] = acc[q][j] + bias;
            }
        }
    }
}

// ---------------------------------------------------------------------------
// Kernel 2: flash attention + residual, FFMA2 core.
// ---------------------------------------------------------------------------
#define QSTR 68
#define PSTR 65

__global__ __launch_bounds__(256) void attn_kernel(
    const float* __restrict__ x, float* __restrict__ out)
{
    extern __shared__ float smem[];
    float* qs     = smem;                  // 64*68
    float* ks     = qs + 64 * QSTR;        // 64*68
    float* vs     = ks + 64 * QSTR;        // 64*256
    float* Ps     = vs + 64 * 256;         // 64*65
    float* corr_s = Ps + 64 * PSTR;        // 64
    float* l_s    = corr_s + 64;           // 64
    float* m_s    = l_s + 64;              // 64

    const int t  = threadIdx.x;
    const int b  = blockIdx.y;
    const int i0 = blockIdx.x * 64;

    const int si  = t >> 2;     // S-phase: row i
    const int sjg = t & 3;      // S-phase: j subgroup
    const int pci = t & 15;     // PV-phase: c group
    const int pti = t >> 4;     // PV-phase: i group

    // load q tile (pre-scaled in proj)
    {
        const float* qg = g_q + ((size_t)b * NN + i0) * DA;
#pragma unroll
        for (int f = t; f < 64 * 16; f += 256) {
            int ii = f >> 4, a4 = f & 15;
            *(float4*)&qs[ii * QSTR + a4 * 4] = *(const float4*)&qg[ii * DA + a4 * 4];
        }
    }
    if (t < 64) { l_s[t] = 0.f; m_s[t] = -1e30f; }

    u64 acc[4][8];   // 4 i-rows x 8 packed c-pairs (16 c)
#pragma unroll
    for (int r = 0; r < 4; r++)
#pragma unroll
        for (int pc = 0; pc < 8; pc++) acc[r][pc] = 0ull;

    for (int j0 = 0; j0 < NN; j0 += 64) {
        __syncthreads();
        {
            const float* kg = g_k + ((size_t)b * NN + j0) * DA;
#pragma unroll
            for (int f = t; f < 64 * 16; f += 256) {
                int jj = f >> 4, a4 = f & 15;
                *(float4*)&ks[jj * QSTR + a4 * 4] = *(const float4*)&kg[jj * DA + a4 * 4];
            }
        }
        {
            const float* vg = g_v + ((size_t)b * NN + j0) * CC;
#pragma unroll
            for (int f = t; f < 64 * 64; f += 256) {
                int jj = f >> 6, c4 = f & 63;
                *(float4*)&vs[jj * 256 + c4 * 4] = *(const float4*)&vg[jj * CC + c4 * 4];
            }
        }
        __syncthreads();

        // ---- S = q . k  (packed over the a-dimension) ----
        u64 sp[16];
#pragma unroll
        for (int jj = 0; jj < 16; jj++) sp[jj] = 0ull;
#pragma unroll
        for (int a4 = 0; a4 < 16; a4++) {
            ulonglong2 q2 = *(ulonglong2*)&qs[si * QSTR + a4 * 4];
#pragma unroll
            for (int jj = 0; jj < 16; jj++) {
                int j = (jj << 2) | sjg;
                ulonglong2 k2 = *(ulonglong2*)&ks[j * QSTR + a4 * 4];
                F2FMA(sp[jj], q2.x, k2.x, sp[jj]);
                F2FMA(sp[jj], q2.y, k2.y, sp[jj]);
            }
        }
        float s[16];
#pragma unroll
        for (int jj = 0; jj < 16; jj++) {
            float lo, hi; F2UNPACK(lo, hi, sp[jj]);
            s[jj] = lo + hi;                      // scale already folded into q
        }

        // ---- online softmax ----
        float rm = -1e30f;
#pragma unroll
        for (int jj = 0; jj < 16; jj++) rm = fmaxf(rm, s[jj]);
        rm = fmaxf(rm, __shfl_xor_sync(0xffffffffu, rm, 1));
        rm = fmaxf(rm, __shfl_xor_sync(0xffffffffu, rm, 2));
        float mold = m_s[si];
        float mnew = fmaxf(mold, rm);
        float rs = 0.f;
#pragma unroll
        for (int jj = 0; jj < 16; jj++) {
            float p = __expf(s[jj] - mnew);
            Ps[si * PSTR + ((jj << 2) | sjg)] = p;
            rs += p;
        }
        rs += __shfl_xor_sync(0xffffffffu, rs, 1);
        rs += __shfl_xor_sync(0xffffffffu, rs, 2);
        float cr = __expf(mold - mnew);
        if (sjg == 0) {
            m_s[si]    = mnew;
            l_s[si]    = l_s[si] * cr + rs;
            corr_s[si] = cr;
        }
        __syncthreads();

        // ---- acc = acc*corr + P V  (packed over the c-dimension) ----
#pragma unroll
        for (int r = 0; r < 4; r++) {
            u64 cp; F2BCAST(cp, corr_s[pti * 4 + r]);
#pragma unroll
            for (int pc = 0; pc < 8; pc++) F2MUL(acc[r][pc], acc[r][pc], cp);
        }
        const float* Prow0 = Ps + (pti * 4 + 0) * PSTR;
        const float* Prow1 = Ps + (pti * 4 + 1) * PSTR;
        const float* Prow2 = Ps + (pti * 4 + 2) * PSTR;
        const float* Prow3 = Ps + (pti * 4 + 3) * PSTR;
        const int vcol = pci * 4;   // contiguous float4 across lanes 0..15
#pragma unroll 4
        for (int j = 0; j < 64; j++) {
            u64 pp0, pp1, pp2, pp3;
            F2BCAST(pp0, Prow0[j]); F2BCAST(pp1, Prow1[j]);
            F2BCAST(pp2, Prow2[j]); F2BCAST(pp3, Prow3[j]);
            const float* vr = vs + j * 256 + vcol;
            ulonglong2 va = *(const ulonglong2*)&vr[0];     // c pairs 0,1
            ulonglong2 vb = *(const ulonglong2*)&vr[64];    // c pairs 2,3
            ulonglong2 vc = *(const ulonglong2*)&vr[128];   // c pairs 4,5
            ulonglong2 vd = *(const ulonglong2*)&vr[192];   // c pairs 6,7
            F2FMA(acc[0][0], pp0, va.x, acc[0][0]); F2FMA(acc[0][1], pp0, va.y, acc[0][1]);
            F2FMA(acc[0][2], pp0, vb.x, acc[0][2]); F2FMA(acc[0][3], pp0, vb.y, acc[0][3]);
            F2FMA(acc[0][4], pp0, vc.x, acc[0][4]); F2FMA(acc[0][5], pp0, vc.y, acc[0][5]);
            F2FMA(acc[0][6], pp0, vd.x, acc[0][6]); F2FMA(acc[0][7], pp0, vd.y, acc[0][7]);

            F2FMA(acc[1][0], pp1, va.x, acc[1][0]); F2FMA(acc[1][1], pp1, va.y, acc[1][1]);
            F2FMA(acc[1][2], pp1, vb.x, acc[1][2]); F2FMA(acc[1][3], pp1, vb.y, acc[1][3]);
            F2FMA(acc[1][4], pp1, vc.x, acc[1][4]); F2FMA(acc[1][5], pp1, vc.y, acc[1][5]);
            F2FMA(acc[1][6], pp1, vd.x, acc[1][6]); F2FMA(acc[1][7], pp1, vd.y, acc[1][7]);

            F2FMA(acc[2][0], pp2, va.x, acc[2][0]); F2FMA(acc[2][1], pp2, va.y, acc[2][1]);
            F2FMA(acc[2][2], pp2, vb.x, acc[2][2]); F2FMA(acc[2][3], pp2, vb.y, acc[2][3]);
            F2FMA(acc[2][4], pp2, vc.x, acc[2][4]); F2FMA(acc[2][5], pp2, vc.y, acc[2][5]);
            F2FMA(acc[2][6], pp2, vd.x, acc[2][6]); F2FMA(acc[2][7], pp2, vd.y, acc[2][7]);

            F2FMA(acc[3][0], pp3, va.x, acc[3][0]); F2FMA(acc[3][1], pp3, va.y, acc[3][1]);
            F2FMA(acc[3][2], pp3, vb.x, acc[3][2]); F2FMA(acc[3][3], pp3, vb.y, acc[3][3]);
            F2FMA(acc[3][4], pp3, vc.x, acc[3][4]); F2FMA(acc[3][5], pp3, vc.y, acc[3][5]);
            F2FMA(acc[3][6], pp3, vd.x, acc[3][6]); F2FMA(acc[3][7], pp3, vd.y, acc[3][7]);
        }
    }

    // ---- epilogue: out[b][c][i] = acc/l + x ----
    float accf[4][16];
#pragma unroll
    for (int r = 0; r < 4; r++)
#pragma unroll
        for (int pc = 0; pc < 8; pc++)
            F2UNPACK(accf[r][2 * pc], accf[r][2 * pc + 1], acc[r][pc]);

    float linv[4];
#pragma unroll
    for (int r = 0; r < 4; r++) linv[r] = 1.0f / l_s[pti * 4 + r];

#pragma unroll
    for (int g = 0; g < 4; g++) {
#pragma unroll
        for (int u = 0; u < 4; u++) {
            int cc = g * 4 + u;
            int c  = g * 64 + pci * 4 + u;
            size_t base = ((size_t)b * CC + c) * NN + i0 + pti * 4;
            float4 xv = *(const float4*)&x[base];
            float4 o;
            o.x = fmaf(accf[0][cc], linv[0], xv.x);
            o.y = fmaf(accf[1][cc], linv[1], xv.y);
            o.z = fmaf(accf[2][cc], linv[2], xv.z);
            o.w = fmaf(accf[3][cc], linv[3], xv.w);
            *(float4*)&out[base] = o;
        }
    }
}

// ---------------------------------------------------------------------------
extern "C" void kernel_launch(void* const* d_in, const int* in_sizes, int n_in,
                              void* d_out, int out_size)
{
    const float* x  = (const float*)d_in[0];
    const float* Wq = (const float*)d_in[1];
    const float* bq = (const float*)d_in[2];
    const float* Wk = (const float*)d_in[3];
    const float* bk = (const float*)d_in[4];
    const float* Wv = (const float*)d_in[5];
    const float* bv = (const float*)d_in[6];
    float* out = (float*)d_out;

    const int smem_bytes = (64 * QSTR + 64 * QSTR + 64 * 256 + 64 * PSTR + 3 * 64) * 4;
    cudaFuncSetAttribute(attn_kernel, cudaFuncAttributeMaxDynamicSharedMemorySize, smem_bytes);

    proj_kernel<<<dim3(64, 3, BB), 256>>>(x, Wq, bq, Wk, bk, Wv, bv);
    attn_kernel<<<dim3(64, BB), 256, smem_bytes>>>(x, out);
}

// round 5
// speedup vs baseline: 5.6744x; 2.9957x over previous
#include <cuda_runtime.h>
#include <cstdint>

#define BB 16
#define CC 256
#define NN 4096
#define DA 64
#define TI 64
#define TJ 64

typedef unsigned long long u64;

// packed fp32x2 ops (proj kernel)
#define F2FMA(d, a, b, c) asm("fma.rn.f32x2 %0, %1, %2, %3;" : "=l"(d) : "l"(a), "l"(b), "l"(c))
#define F2BCAST(d, s)     asm("mov.b64 %0, {%1, %1};" : "=l"(d) : "r"(__float_as_uint(s)))
#define F2UNPACK(lo, hi, v) asm("mov.b64 {%0, %1}, %2;" : "=f"(lo), "=f"(hi) : "l"(v))

// tf32 mma.sync (sm_80+; works on plain sm_103 target)
#define MMA_TF32(d0,d1,d2,d3,a0,a1,a2,a3,b0,b1) \
    asm volatile("mma.sync.aligned.m16n8k8.row.col.f32.tf32.tf32.f32 " \
        "{%0,%1,%2,%3}, {%4,%5,%6,%7}, {%8,%9}, {%0,%1,%2,%3};" \
        : "+f"(d0), "+f"(d1), "+f"(d2), "+f"(d3) \
        : "r"(a0), "r"(a1), "r"(a2), "r"(a3), "r"(b0), "r"(b1))

// Scratch
__device__ float g_q[(size_t)BB * NN * DA];   // [b][n][a]  (pre-scaled by log2e/64)
__device__ float g_k[(size_t)BB * NN * DA];   // [b][n][a]
__device__ float g_v[(size_t)BB * CC * NN];   // [b][c][n]  TRANSPOSED

// ---------------------------------------------------------------------------
// Kernel 1: fused QKV projection (FFMA2) — v written transposed [b][c][n]
// ---------------------------------------------------------------------------
__global__ __launch_bounds__(256) void proj_kernel(
    const float* __restrict__ x,
    const float* __restrict__ Wq, const float* __restrict__ bq,
    const float* __restrict__ Wk, const float* __restrict__ bk,
    const float* __restrict__ Wv, const float* __restrict__ bv)
{
    __shared__ float xs[64][64];
    __shared__ float ws[128][64];

    const int t  = threadIdx.x;
    const int nt = blockIdx.x;
    const int rg = blockIdx.y;
    const int b  = blockIdx.z;
    const int n0 = nt * 64;
    const int tn = t & 15;
    const int tr = t >> 4;

    u64 accp[8][2];
#pragma unroll
    for (int q = 0; q < 8; q++) { accp[q][0] = 0ull; accp[q][1] = 0ull; }

    for (int c0 = 0; c0 < CC; c0 += 64) {
        __syncthreads();
#pragma unroll
        for (int f = t; f < 64 * 16; f += 256) {
            int cc = f >> 4, n4 = f & 15;
            *(float4*)&xs[cc][n4 * 4] =
                *(const float4*)&x[((size_t)b * CC + (c0 + cc)) * NN + n0 + n4 * 4];
        }
#pragma unroll
        for (int f = t; f < 128 * 16; f += 256) {
            int r = f >> 4, c4 = f & 15;
            const float* wp;
            if (rg == 0) wp = (r < 64) ? (Wq + r * CC) : (Wk + (r - 64) * CC);
            else         wp = Wv + ((size_t)((rg - 1) * 128 + r)) * CC;
            *(float4*)&ws[r][c4 * 4] = *(const float4*)&wp[c0 + c4 * 4];
        }
        __syncthreads();
#pragma unroll 8
        for (int cc = 0; cc < 64; cc++) {
            ulonglong2 xp = *(ulonglong2*)&xs[cc][tn * 4];
#pragma unroll
            for (int q = 0; q < 8; q++) {
                u64 wpk; F2BCAST(wpk, ws[tr * 8 + q][cc]);
                F2FMA(accp[q][0], wpk, xp.x, accp[q][0]);
                F2FMA(accp[q][1], wpk, xp.y, accp[q][1]);
            }
        }
    }

    float acc[8][4];
#pragma unroll
    for (int q = 0; q < 8; q++) {
        F2UNPACK(acc[q][0], acc[q][1], accp[q][0]);
        F2UNPACK(acc[q][2], acc[q][3], accp[q][1]);
    }

    const float qscale = 1.4426950408889634f / 64.0f;  // log2(e)/sqrt(N)
#pragma unroll
    for (int q = 0; q < 8; q++) {
        int r = tr * 8 + q;
        if (rg == 0) {
            if (r < 64) {
                float bias = bq[r];
                float* dst = g_q + (size_t)b * NN * DA;
#pragma unroll
                for (int j = 0; j < 4; j++) {
                    int n = n0 + tn * 4 + j;
                    dst[(size_t)n * DA + r] = (acc[q][j] + bias) * qscale;
                }
            } else {
                float bias = bk[r - 64];
                float* dst = g_k + (size_t)b * NN * DA;
#pragma unroll
                for (int j = 0; j < 4; j++) {
                    int n = n0 + tn * 4 + j;
                    dst[(size_t)n * DA + (r - 64)] = acc[q][j] + bias;
                }
            }
        } else {
            int c = (rg - 1) * 128 + r;
            float bias = bv[c];
            float4 st;
            st.x = acc[q][0] + bias; st.y = acc[q][1] + bias;
            st.z = acc[q][2] + bias; st.w = acc[q][3] + bias;
            *(float4*)&g_v[((size_t)b * CC + c) * NN + n0 + tn * 4] = st;
        }
    }
}

// ---------------------------------------------------------------------------
// Kernel 2: mma.sync tf32 flash attention (max-free softmax) + residual.
// Grid (64, 16), 256 threads = 8 warps: wr = wid&3 (16 i-rows), wc = wid>>2
// (j-half for S, c-half for O). O accumulates in f32 regs across all tiles.
// ---------------------------------------------------------------------------
#define KSTR 68   // ks row stride (words): conflict-free B-frag reads
#define VSTR 76   // vs row stride: conflict-free B-frag reads
#define PSTR 68   // ps row stride: conflict-free A-frag reads

__global__ __launch_bounds__(256, 1) void attn_kernel(
    const float* __restrict__ x, float* __restrict__ out)
{
    extern __shared__ __align__(16) float sm[];
    float* ks   = sm;                        // [64][KSTR]
    float* vs   = ks + TJ * KSTR;            // [256][VSTR]
    float* ps   = vs + CC * VSTR;            // [64][PSTR]
    float* lsum = ps + TI * PSTR;            // [2][64]

    const int t    = threadIdx.x;
    const int lane = t & 31;
    const int wid  = t >> 5;
    const int g    = lane >> 2;    // groupID (row within fragment)
    const int tg   = lane & 3;     // thread-in-group
    const int wr   = wid & 3;      // i-block: rows wr*16 .. +15
    const int wc   = wid >> 2;     // j-half (S) / c-half (O)
    const int b    = blockIdx.y;
    const int i0   = blockIdx.x * TI;

    // ---- Q fragments in registers, loaded once ----
    uint32_t qa[8][4];
    {
        const float* qg = g_q + ((size_t)b * NN + i0 + wr * 16) * DA;
#pragma unroll
        for (int s = 0; s < 8; s++) {
            qa[s][0] = __float_as_uint(qg[(size_t)(g    ) * DA + 8 * s + tg    ]);
            qa[s][1] = __float_as_uint(qg[(size_t)(g + 8) * DA + 8 * s + tg    ]);
            qa[s][2] = __float_as_uint(qg[(size_t)(g    ) * DA + 8 * s + tg + 4]);
            qa[s][3] = __float_as_uint(qg[(size_t)(g + 8) * DA + 8 * s + tg + 4]);
        }
    }

    float o[16][4];
#pragma unroll
    for (int n = 0; n < 16; n++)
#pragma unroll
        for (int r = 0; r < 4; r++) o[n][r] = 0.f;

    float l0 = 0.f, l1 = 0.f;

    for (int jt = 0; jt < NN / TJ; jt++) {
        const int j0 = jt * TJ;
        __syncthreads();   // previous PV done before overwriting ks/vs
        // ---- stage K [64j x 64a] ----
        {
            const float* kg = g_k + ((size_t)b * NN + j0) * DA;
#pragma unroll
            for (int f = t; f < TJ * 16; f += 256) {
                int r = f >> 4, a4 = f & 15;
                *(float4*)&ks[r * KSTR + a4 * 4] = *(const float4*)&kg[(size_t)r * DA + a4 * 4];
            }
        }
        // ---- stage V [256c x 64j] (from transposed g_v) ----
        {
            const float* vg = g_v + (size_t)b * CC * NN + j0;
#pragma unroll
            for (int f = t; f < CC * 16; f += 256) {
                int c = f >> 4, j4 = f & 15;
                *(float4*)&vs[c * VSTR + j4 * 4] = *(const float4*)&vg[(size_t)c * NN + j4 * 4];
            }
        }
        __syncthreads();

        // ---- S = Q K^T : warp covers rows wr*16..+15, cols wc*32..+31 ----
        float sf[4][4];
#pragma unroll
        for (int n = 0; n < 4; n++)
#pragma unroll
            for (int r = 0; r < 4; r++) sf[n][r] = 0.f;
#pragma unroll
        for (int s = 0; s < 8; s++) {
#pragma unroll
            for (int n = 0; n < 4; n++) {
                const float* kb = &ks[(wc * 32 + n * 8 + g) * KSTR + 8 * s + tg];
                uint32_t b0 = __float_as_uint(kb[0]);
                uint32_t b1 = __float_as_uint(kb[4]);
                MMA_TF32(sf[n][0], sf[n][1], sf[n][2], sf[n][3],
                         qa[s][0], qa[s][1], qa[s][2], qa[s][3], b0, b1);
            }
        }

        // ---- exp (base-2, scale pre-folded) + P to smem + partial row sums ----
#pragma unroll
        for (int n = 0; n < 4; n++) {
            float p0, p1, p2, p3;
            asm("ex2.approx.ftz.f32 %0, %1;" : "=f"(p0) : "f"(sf[n][0]));
            asm("ex2.approx.ftz.f32 %0, %1;" : "=f"(p1) : "f"(sf[n][1]));
            asm("ex2.approx.ftz.f32 %0, %1;" : "=f"(p2) : "f"(sf[n][2]));
            asm("ex2.approx.ftz.f32 %0, %1;" : "=f"(p3) : "f"(sf[n][3]));
            l0 += p0 + p1;
            l1 += p2 + p3;
            int col = wc * 32 + n * 8 + 2 * tg;
            *(float2*)&ps[(wr * 16 + g    ) * PSTR + col] = make_float2(p0, p1);
            *(float2*)&ps[(wr * 16 + g + 8) * PSTR + col] = make_float2(p2, p3);
        }
        __syncthreads();

        // ---- O += P V : warp covers rows wr*16..+15, cols wc*128..+127 ----
#pragma unroll
        for (int s = 0; s < 8; s++) {
            const float* pr = &ps[(wr * 16 + g) * PSTR + 8 * s + tg];
            uint32_t a0 = __float_as_uint(pr[0]);
            uint32_t a2 = __float_as_uint(pr[4]);
            uint32_t a1 = __float_as_uint(pr[8 * PSTR]);
            uint32_t a3 = __float_as_uint(pr[8 * PSTR + 4]);
#pragma unroll
            for (int n = 0; n < 16; n++) {
                const float* vb = &vs[(wc * 128 + n * 8 + g) * VSTR + 8 * s + tg];
                uint32_t b0 = __float_as_uint(vb[0]);
                uint32_t b1 = __float_as_uint(vb[4]);
                MMA_TF32(o[n][0], o[n][1], o[n][2], o[n][3], a0, a1, a2, a3, b0, b1);
            }
        }
    }

    // ---- reduce l across the two wc warp-halves ----
    l0 += __shfl_xor_sync(0xffffffffu, l0, 1);
    l0 += __shfl_xor_sync(0xffffffffu, l0, 2);
    l1 += __shfl_xor_sync(0xffffffffu, l1, 1);
    l1 += __shfl_xor_sync(0xffffffffu, l1, 2);
    __syncthreads();
    if (tg == 0) {
        lsum[wc * 64 + wr * 16 + g    ] = l0;
        lsum[wc * 64 + wr * 16 + g + 8] = l1;
    }
    __syncthreads();
    const float linv0 = 1.0f / (lsum[wr * 16 + g    ] + lsum[64 + wr * 16 + g    ]);
    const float linv1 = 1.0f / (lsum[wr * 16 + g + 8] + lsum[64 + wr * 16 + g + 8]);

    // ---- epilogue: out[b][c][i] = O/l + x ----
    const int r0 = i0 + wr * 16 + g;
#pragma unroll
    for (int n = 0; n < 16; n++) {
        int c = wc * 128 + n * 8 + 2 * tg;
        size_t b0i = ((size_t)b * CC + c) * NN;
        size_t b1i = ((size_t)b * CC + c + 1) * NN;
        out[b0i + r0]     = fmaf(o[n][0], linv0, x[b0i + r0]);
        out[b1i + r0]     = fmaf(o[n][1], linv0, x[b1i + r0]);
        out[b0i + r0 + 8] = fmaf(o[n][2], linv1, x[b0i + r0 + 8]);
        out[b1i + r0 + 8] = fmaf(o[n][3], linv1, x[b1i + r0 + 8]);
    }
}

// ---------------------------------------------------------------------------
extern "C" void kernel_launch(void* const* d_in, const int* in_sizes, int n_in,
                              void* d_out, int out_size)
{
    const float* x  = (const float*)d_in[0];
    const float* Wq = (const float*)d_in[1];
    const float* bq = (const float*)d_in[2];
    const float* Wk = (const float*)d_in[3];
    const float* bk = (const float*)d_in[4];
    const float* Wv = (const float*)d_in[5];
    const float* bv = (const float*)d_in[6];
    float* out = (float*)d_out;

    const int smem_bytes = (TJ * KSTR + CC * VSTR + TI * PSTR + 2 * 64) * 4;
    cudaFuncSetAttribute(attn_kernel, cudaFuncAttributeMaxDynamicSharedMemorySize, smem_bytes);

    proj_kernel<<<dim3(64, 3, BB), 256>>>(x, Wq, bq, Wk, bk, Wv, bv);
    attn_kernel<<<dim3(NN / TI, BB), 256, smem_bytes>>>(x, out);
}

// round 6
// speedup vs baseline: 6.0461x; 1.0655x over previous
#include <cuda_runtime.h>
#include <cuda_bf16.h>
#include <cstdint>

#define BB 16
#define CC 256
#define NN 4096
#define DA 64
#define TI 64
#define TJ 64

typedef unsigned long long u64;

// packed fp32x2 ops (proj kernel)
#define F2FMA(d, a, b, c) asm("fma.rn.f32x2 %0, %1, %2, %3;" : "=l"(d) : "l"(a), "l"(b), "l"(c))
#define F2BCAST(d, s)     asm("mov.b64 %0, {%1, %1};" : "=l"(d) : "r"(__float_as_uint(s)))
#define F2UNPACK(lo, hi, v) asm("mov.b64 {%0, %1}, %2;" : "=f"(lo), "=f"(hi) : "l"(v))

// bf16 mma.sync m16n8k16 (sm_80+; works on plain sm_103 target)
#define MMA_BF16(d0,d1,d2,d3,a0,a1,a2,a3,b0,b1) \
    asm volatile("mma.sync.aligned.m16n8k16.row.col.f32.bf16.bf16.f32 " \
        "{%0,%1,%2,%3}, {%4,%5,%6,%7}, {%8,%9}, {%0,%1,%2,%3};" \
        : "+f"(d0), "+f"(d1), "+f"(d2), "+f"(d3) \
        : "r"(a0), "r"(a1), "r"(a2), "r"(a3), "r"(b0), "r"(b1))

// pack two f32 -> bf16x2 (lo in [15:0], hi in [31:16])
#define PACK_BF16X2(d, lo, hi) \
    asm("cvt.rn.bf16x2.f32 %0, %1, %2;" : "=r"(d) : "f"(hi), "f"(lo))

// Scratch (bf16)
__device__ __nv_bfloat16 g_q[(size_t)BB * NN * DA];   // [b][n][a] (pre-scaled log2e/64)
__device__ __nv_bfloat16 g_k[(size_t)BB * NN * DA];   // [b][n][a]
__device__ __nv_bfloat16 g_v[(size_t)BB * CC * NN];   // [b][c][n] TRANSPOSED

// ---------------------------------------------------------------------------
// Kernel 1: fused QKV projection (FFMA2, fp32 math) -> bf16 outputs
// ---------------------------------------------------------------------------
__global__ __launch_bounds__(256) void proj_kernel(
    const float* __restrict__ x,
    const float* __restrict__ Wq, const float* __restrict__ bq,
    const float* __restrict__ Wk, const float* __restrict__ bk,
    const float* __restrict__ Wv, const float* __restrict__ bv)
{
    __shared__ float xs[64][64];
    __shared__ float ws[128][64];

    const int t  = threadIdx.x;
    const int nt = blockIdx.x;
    const int rg = blockIdx.y;
    const int b  = blockIdx.z;
    const int n0 = nt * 64;
    const int tn = t & 15;
    const int tr = t >> 4;

    u64 accp[8][2];
#pragma unroll
    for (int q = 0; q < 8; q++) { accp[q][0] = 0ull; accp[q][1] = 0ull; }

    for (int c0 = 0; c0 < CC; c0 += 64) {
        __syncthreads();
#pragma unroll
        for (int f = t; f < 64 * 16; f += 256) {
            int cc = f >> 4, n4 = f & 15;
            *(float4*)&xs[cc][n4 * 4] =
                *(const float4*)&x[((size_t)b * CC + (c0 + cc)) * NN + n0 + n4 * 4];
        }
#pragma unroll
        for (int f = t; f < 128 * 16; f += 256) {
            int r = f >> 4, c4 = f & 15;
            const float* wp;
            if (rg == 0) wp = (r < 64) ? (Wq + r * CC) : (Wk + (r - 64) * CC);
            else         wp = Wv + ((size_t)((rg - 1) * 128 + r)) * CC;
            *(float4*)&ws[r][c4 * 4] = *(const float4*)&wp[c0 + c4 * 4];
        }
        __syncthreads();
#pragma unroll 8
        for (int cc = 0; cc < 64; cc++) {
            ulonglong2 xp = *(ulonglong2*)&xs[cc][tn * 4];
#pragma unroll
            for (int q = 0; q < 8; q++) {
                u64 wpk; F2BCAST(wpk, ws[tr * 8 + q][cc]);
                F2FMA(accp[q][0], wpk, xp.x, accp[q][0]);
                F2FMA(accp[q][1], wpk, xp.y, accp[q][1]);
            }
        }
    }

    float acc[8][4];
#pragma unroll
    for (int q = 0; q < 8; q++) {
        F2UNPACK(acc[q][0], acc[q][1], accp[q][0]);
        F2UNPACK(acc[q][2], acc[q][3], accp[q][1]);
    }

    const float qscale = 1.4426950408889634f / 64.0f;  // log2(e)/sqrt(N)
#pragma unroll
    for (int q = 0; q < 8; q++) {
        int r = tr * 8 + q;
        if (rg == 0) {
            if (r < 64) {
                float bias = bq[r];
                __nv_bfloat16* dst = g_q + (size_t)b * NN * DA;
#pragma unroll
                for (int j = 0; j < 4; j++) {
                    int n = n0 + tn * 4 + j;
                    dst[(size_t)n * DA + r] = __float2bfloat16((acc[q][j] + bias) * qscale);
                }
            } else {
                float bias = bk[r - 64];
                __nv_bfloat16* dst = g_k + (size_t)b * NN * DA;
#pragma unroll
                for (int j = 0; j < 4; j++) {
                    int n = n0 + tn * 4 + j;
                    dst[(size_t)n * DA + (r - 64)] = __float2bfloat16(acc[q][j] + bias);
                }
            }
        } else {
            int c = (rg - 1) * 128 + r;
            float bias = bv[c];
            uint2 st;
            PACK_BF16X2(st.x, acc[q][0] + bias, acc[q][1] + bias);
            PACK_BF16X2(st.y, acc[q][2] + bias, acc[q][3] + bias);
            *(uint2*)&g_v[((size_t)b * CC + c) * NN + n0 + tn * 4] = st;
        }
    }
}

// ---------------------------------------------------------------------------
// Kernel 2: bf16 mma.sync flash attention (max-free softmax) + residual.
// Grid (64, 16), 256 threads = 8 warps: wr = wid&3 (16 i-rows), wc = wid>>2.
// smem rows stride 36 words -> all fragment access patterns hit 32 banks once.
// ---------------------------------------------------------------------------
#define STR 36   // row stride in 32-bit words (32 data words + 4 pad)

__global__ __launch_bounds__(256, 1) void attn_kernel(
    const float* __restrict__ x, float* __restrict__ out)
{
    extern __shared__ __align__(16) uint32_t sm[];
    uint32_t* ks   = sm;                      // [64][STR]  K tile bf16x2
    uint32_t* vs   = ks + TJ * STR;           // [256][STR] V tile bf16x2
    uint32_t* ps   = vs + CC * STR;           // [64][STR]  P tile bf16x2
    float*    lsum = (float*)(ps + TI * STR); // [2][64]

    const int t    = threadIdx.x;
    const int lane = t & 31;
    const int wid  = t >> 5;
    const int g    = lane >> 2;
    const int tg   = lane & 3;
    const int wr   = wid & 3;
    const int wc   = wid >> 2;
    const int b    = blockIdx.y;
    const int i0   = blockIdx.x * TI;

    // ---- Q fragments in registers (4 k16-steps), loaded once ----
    uint32_t qa[4][4];
    {
        const __nv_bfloat16* qg = g_q + ((size_t)b * NN + i0 + wr * 16) * DA;
#pragma unroll
        for (int s = 0; s < 4; s++) {
            qa[s][0] = *(const uint32_t*)&qg[(size_t)(g    ) * DA + s * 16 + 2 * tg    ];
            qa[s][1] = *(const uint32_t*)&qg[(size_t)(g + 8) * DA + s * 16 + 2 * tg    ];
            qa[s][2] = *(const uint32_t*)&qg[(size_t)(g    ) * DA + s * 16 + 2 * tg + 8];
            qa[s][3] = *(const uint32_t*)&qg[(size_t)(g + 8) * DA + s * 16 + 2 * tg + 8];
        }
    }

    float o[16][4];
#pragma unroll
    for (int n = 0; n < 16; n++)
#pragma unroll
        for (int r = 0; r < 4; r++) o[n][r] = 0.f;

    float l0 = 0.f, l1 = 0.f;

    for (int jt = 0; jt < NN / TJ; jt++) {
        const int j0 = jt * TJ;
        __syncthreads();
        // ---- stage K [64j x 64a] bf16 (16B/lane, row-inner for bank spread) ----
        {
            const __nv_bfloat16* kg = g_k + ((size_t)b * NN + j0) * DA;
#pragma unroll
            for (int f = t; f < 512; f += 256) {
                int r = f & 63, c4 = f >> 6;
                *(uint4*)&ks[r * STR + c4 * 4] = *(const uint4*)&kg[(size_t)r * DA + c4 * 8];
            }
        }
        // ---- stage V [256c x 64j] bf16 ----
        {
            const __nv_bfloat16* vg = g_v + (size_t)b * CC * NN + j0;
#pragma unroll
            for (int f = t; f < 2048; f += 256) {
                int c = f & 255, c4 = f >> 8;
                *(uint4*)&vs[c * STR + c4 * 4] = *(const uint4*)&vg[(size_t)c * NN + c4 * 8];
            }
        }
        __syncthreads();

        // ---- S = Q K^T : rows wr*16..+15, cols wc*32..+31 (4 k16-steps) ----
        float sf[4][4];
#pragma unroll
        for (int n = 0; n < 4; n++)
#pragma unroll
            for (int r = 0; r < 4; r++) sf[n][r] = 0.f;
#pragma unroll
        for (int s = 0; s < 4; s++) {
#pragma unroll
            for (int n = 0; n < 4; n++) {
                const uint32_t* kb = &ks[(wc * 32 + n * 8 + g) * STR + s * 8 + tg];
                MMA_BF16(sf[n][0], sf[n][1], sf[n][2], sf[n][3],
                         qa[s][0], qa[s][1], qa[s][2], qa[s][3], kb[0], kb[4]);
            }
        }

        // ---- exp (base-2, scale pre-folded) + P (bf16x2) + partial row sums ----
#pragma unroll
        for (int n = 0; n < 4; n++) {
            float p0, p1, p2, p3;
            asm("ex2.approx.ftz.f32 %0, %1;" : "=f"(p0) : "f"(sf[n][0]));
            asm("ex2.approx.ftz.f32 %0, %1;" : "=f"(p1) : "f"(sf[n][1]));
            asm("ex2.approx.ftz.f32 %0, %1;" : "=f"(p2) : "f"(sf[n][2]));
            asm("ex2.approx.ftz.f32 %0, %1;" : "=f"(p3) : "f"(sf[n][3]));
            l0 += p0 + p1;
            l1 += p2 + p3;
            int colw = wc * 16 + n * 4 + tg;
            uint32_t pk0, pk1;
            PACK_BF16X2(pk0, p0, p1);
            PACK_BF16X2(pk1, p2, p3);
            ps[(wr * 16 + g    ) * STR + colw] = pk0;
            ps[(wr * 16 + g + 8) * STR + colw] = pk1;
        }
        __syncthreads();

        // ---- O += P V : rows wr*16..+15, cols wc*128..+127 (4 k16-steps) ----
#pragma unroll
        for (int s = 0; s < 4; s++) {
            const uint32_t* pr = &ps[(wr * 16 + g) * STR + s * 8 + tg];
            uint32_t a0 = pr[0];
            uint32_t a2 = pr[4];
            uint32_t a1 = pr[8 * STR];
            uint32_t a3 = pr[8 * STR + 4];
#pragma unroll
            for (int n = 0; n < 16; n++) {
                const uint32_t* vb = &vs[(wc * 128 + n * 8 + g) * STR + s * 8 + tg];
                MMA_BF16(o[n][0], o[n][1], o[n][2], o[n][3], a0, a1, a2, a3, vb[0], vb[4]);
            }
        }
    }

    // ---- reduce l across the two wc warp-halves ----
    l0 += __shfl_xor_sync(0xffffffffu, l0, 1);
    l0 += __shfl_xor_sync(0xffffffffu, l0, 2);
    l1 += __shfl_xor_sync(0xffffffffu, l1, 1);
    l1 += __shfl_xor_sync(0xffffffffu, l1, 2);
    __syncthreads();
    if (tg == 0) {
        lsum[wc * 64 + wr * 16 + g    ] = l0;
        lsum[wc * 64 + wr * 16 + g + 8] = l1;
    }
    __syncthreads();
    const float linv0 = 1.0f / (lsum[wr * 16 + g    ] + lsum[64 + wr * 16 + g    ]);
    const float linv1 = 1.0f / (lsum[wr * 16 + g + 8] + lsum[64 + wr * 16 + g + 8]);

    // ---- epilogue: out[b][c][i] = O/l + x ----
    const int r0 = i0 + wr * 16 + g;
#pragma unroll
    for (int n = 0; n < 16; n++) {
        int c = wc * 128 + n * 8 + 2 * tg;
        size_t b0i = ((size_t)b * CC + c) * NN;
        size_t b1i = ((size_t)b * CC + c + 1) * NN;
        out[b0i + r0]     = fmaf(o[n][0], linv0, x[b0i + r0]);
        out[b1i + r0]     = fmaf(o[n][1], linv0, x[b1i + r0]);
        out[b0i + r0 + 8] = fmaf(o[n][2], linv1, x[b0i + r0 + 8]);
        out[b1i + r0 + 8] = fmaf(o[n][3], linv1, x[b1i + r0 + 8]);
    }
}

// ---------------------------------------------------------------------------
extern "C" void kernel_launch(void* const* d_in, const int* in_sizes, int n_in,
                              void* d_out, int out_size)
{
    const float* x  = (const float*)d_in[0];
    const float* Wq = (const float*)d_in[1];
    const float* bq = (const float*)d_in[2];
    const float* Wk = (const float*)d_in[3];
    const float* bk = (const float*)d_in[4];
    const float* Wv = (const float*)d_in[5];
    const float* bv = (const float*)d_in[6];
    float* out = (float*)d_out;

    const int smem_bytes = (TJ * STR + CC * STR + TI * STR + 2 * 64) * 4;
    cudaFuncSetAttribute(attn_kernel, cudaFuncAttributeMaxDynamicSharedMemorySize, smem_bytes);

    proj_kernel<<<dim3(64, 3, BB), 256>>>(x, Wq, bq, Wk, bk, Wv, bv);
    attn_kernel<<<dim3(NN / TI, BB), 256, smem_bytes>>>(x, out);
}

// round 7
// speedup vs baseline: 7.4029x; 1.2244x over previous
#include <cuda_runtime.h>
#include <cuda_bf16.h>
#include <cstdint>

#define BB 16
#define CC 256
#define NN 4096
#define DA 64
#define TI 64
#define TJ 64

typedef unsigned long long u64;

// packed fp32x2 ops (proj kernel)
#define F2FMA(d, a, b, c) asm("fma.rn.f32x2 %0, %1, %2, %3;" : "=l"(d) : "l"(a), "l"(b), "l"(c))
#define F2BCAST(d, s)     asm("mov.b64 %0, {%1, %1};" : "=l"(d) : "r"(__float_as_uint(s)))
#define F2UNPACK(lo, hi, v) asm("mov.b64 {%0, %1}, %2;" : "=f"(lo), "=f"(hi) : "l"(v))

#define MMA_BF16(d0,d1,d2,d3,a0,a1,a2,a3,b0,b1) \
    asm volatile("mma.sync.aligned.m16n8k16.row.col.f32.bf16.bf16.f32 " \
        "{%0,%1,%2,%3}, {%4,%5,%6,%7}, {%8,%9}, {%0,%1,%2,%3};" \
        : "+f"(d0), "+f"(d1), "+f"(d2), "+f"(d3) \
        : "r"(a0), "r"(a1), "r"(a2), "r"(a3), "r"(b0), "r"(b1))

#define PACK_BF16X2(d, lo, hi) \
    asm("cvt.rn.bf16x2.f32 %0, %1, %2;" : "=r"(d) : "f"(hi), "f"(lo))

// cp.async (sm_80+)
#define CP_ASYNC16(dst, src) \
    asm volatile("cp.async.cg.shared.global [%0], [%1], 16;" :: "r"(dst), "l"(src) : "memory")
#define CP_COMMIT() asm volatile("cp.async.commit_group;" ::: "memory")
#define CP_WAIT(n)  asm volatile("cp.async.wait_group %0;" :: "n"(n) : "memory")

// Scratch (bf16)
__device__ __nv_bfloat16 g_q[(size_t)BB * NN * DA];   // [b][n][a] (pre-scaled log2e/64)
__device__ __nv_bfloat16 g_k[(size_t)BB * NN * DA];   // [b][n][a]
__device__ __nv_bfloat16 g_v[(size_t)BB * CC * NN];   // [b][c][n] TRANSPOSED

// ---------------------------------------------------------------------------
// Kernel 1: fused QKV projection (FFMA2, fp32 math) -> bf16 outputs
// ---------------------------------------------------------------------------
__global__ __launch_bounds__(256) void proj_kernel(
    const float* __restrict__ x,
    const float* __restrict__ Wq, const float* __restrict__ bq,
    const float* __restrict__ Wk, const float* __restrict__ bk,
    const float* __restrict__ Wv, const float* __restrict__ bv)
{
    __shared__ float xs[64][64];
    __shared__ float ws[128][64];

    const int t  = threadIdx.x;
    const int nt = blockIdx.x;
    const int rg = blockIdx.y;
    const int b  = blockIdx.z;
    const int n0 = nt * 64;
    const int tn = t & 15;
    const int tr = t >> 4;

    u64 accp[8][2];
#pragma unroll
    for (int q = 0; q < 8; q++) { accp[q][0] = 0ull; accp[q][1] = 0ull; }

    for (int c0 = 0; c0 < CC; c0 += 64) {
        __syncthreads();
#pragma unroll
        for (int f = t; f < 64 * 16; f += 256) {
            int cc = f >> 4, n4 = f & 15;
            *(float4*)&xs[cc][n4 * 4] =
                *(const float4*)&x[((size_t)b * CC + (c0 + cc)) * NN + n0 + n4 * 4];
        }
#pragma unroll
        for (int f = t; f < 128 * 16; f += 256) {
            int r = f >> 4, c4 = f & 15;
            const float* wp;
            if (rg == 0) wp = (r < 64) ? (Wq + r * CC) : (Wk + (r - 64) * CC);
            else         wp = Wv + ((size_t)((rg - 1) * 128 + r)) * CC;
            *(float4*)&ws[r][c4 * 4] = *(const float4*)&wp[c0 + c4 * 4];
        }
        __syncthreads();
#pragma unroll 8
        for (int cc = 0; cc < 64; cc++) {
            ulonglong2 xp = *(ulonglong2*)&xs[cc][tn * 4];
#pragma unroll
            for (int q = 0; q < 8; q++) {
                u64 wpk; F2BCAST(wpk, ws[tr * 8 + q][cc]);
                F2FMA(accp[q][0], wpk, xp.x, accp[q][0]);
                F2FMA(accp[q][1], wpk, xp.y, accp[q][1]);
            }
        }
    }

    float acc[8][4];
#pragma unroll
    for (int q = 0; q < 8; q++) {
        F2UNPACK(acc[q][0], acc[q][1], accp[q][0]);
        F2UNPACK(acc[q][2], acc[q][3], accp[q][1]);
    }

    const float qscale = 1.4426950408889634f / 64.0f;  // log2(e)/sqrt(N)
#pragma unroll
    for (int q = 0; q < 8; q++) {
        int r = tr * 8 + q;
        if (rg == 0) {
            if (r < 64) {
                float bias = bq[r];
                __nv_bfloat16* dst = g_q + (size_t)b * NN * DA;
#pragma unroll
                for (int j = 0; j < 4; j++) {
                    int n = n0 + tn * 4 + j;
                    dst[(size_t)n * DA + r] = __float2bfloat16((acc[q][j] + bias) * qscale);
                }
            } else {
                float bias = bk[r - 64];
                __nv_bfloat16* dst = g_k + (size_t)b * NN * DA;
#pragma unroll
                for (int j = 0; j < 4; j++) {
                    int n = n0 + tn * 4 + j;
                    dst[(size_t)n * DA + (r - 64)] = __float2bfloat16(acc[q][j] + bias);
                }
            }
        } else {
            int c = (rg - 1) * 128 + r;
            float bias = bv[c];
            uint2 st;
            PACK_BF16X2(st.x, acc[q][0] + bias, acc[q][1] + bias);
            PACK_BF16X2(st.y, acc[q][2] + bias, acc[q][3] + bias);
            *(uint2*)&g_v[((size_t)b * CC + c) * NN + n0 + tn * 4] = st;
        }
    }
}

// ---------------------------------------------------------------------------
// Kernel 2: bf16 mma.sync flash attention, cp.async double-buffered, 2 CTA/SM.
// S warp grid: 4(rows of 16) x 2(col halves of 32).
// PV warp grid: 2(rows of 32) x 4(col groups of 64) — halves V B-frag traffic.
// ---------------------------------------------------------------------------
#define STR 36           // row stride (words): conflict-free everywhere
#define KW  (TJ * STR)   // 2304 words
#define VW  (CC * STR)   // 9216 words
#define OKS0 0
#define OVS0 (OKS0 + KW)
#define OKS1 (OVS0 + VW)
#define OVS1 (OKS1 + KW)
#define OPS  (OVS1 + VW)
#define OLS  (OPS + TI * STR)
#define SMW  (OLS + 2 * 64)     // total words

__device__ __forceinline__ uint32_t smem_u32(const void* p) {
    uint32_t a;
    asm("{ .reg .u64 t; cvta.to.shared.u64 t, %1; cvt.u32.u64 %0, t; }" : "=r"(a) : "l"(p));
    return a;
}

__global__ __launch_bounds__(256, 2) void attn_kernel(
    const float* __restrict__ x, float* __restrict__ out)
{
    extern __shared__ __align__(16) uint32_t sm[];
    const uint32_t smb = smem_u32(sm);

    const int t    = threadIdx.x;
    const int lane = t & 31;
    const int wid  = t >> 5;
    const int g    = lane >> 2;
    const int tg   = lane & 3;
    const int wr   = wid & 3;      // S rows: wr*16
    const int wc   = wid >> 2;     // S cols: wc*32
    const int rg2  = wid & 1;      // PV rows: rg2*32
    const int cg2  = wid >> 1;     // PV cols: cg2*64
    const int b    = blockIdx.y;
    const int i0   = blockIdx.x * TI;

    // ---- Q fragments in registers (4 k16-steps), loaded once ----
    uint32_t qa[4][4];
    {
        const __nv_bfloat16* qg = g_q + ((size_t)b * NN + i0 + wr * 16) * DA;
#pragma unroll
        for (int s = 0; s < 4; s++) {
            qa[s][0] = *(const uint32_t*)&qg[(size_t)(g    ) * DA + s * 16 + 2 * tg    ];
            qa[s][1] = *(const uint32_t*)&qg[(size_t)(g + 8) * DA + s * 16 + 2 * tg    ];
            qa[s][2] = *(const uint32_t*)&qg[(size_t)(g    ) * DA + s * 16 + 2 * tg + 8];
            qa[s][3] = *(const uint32_t*)&qg[(size_t)(g + 8) * DA + s * 16 + 2 * tg + 8];
        }
    }

    float o[2][8][4];
#pragma unroll
    for (int blk = 0; blk < 2; blk++)
#pragma unroll
        for (int n = 0; n < 8; n++)
#pragma unroll
            for (int r = 0; r < 4; r++) o[blk][n][r] = 0.f;

    float l0 = 0.f, l1 = 0.f;

    const __nv_bfloat16* kgb = g_k + (size_t)b * NN * DA;
    const __nv_bfloat16* vgb = g_v + (size_t)b * CC * NN;

    // ---- prologue: stage tile 0 into buffer 0 ----
    {
        const __nv_bfloat16* kg = kgb;
        uint32_t kdst = smb + OKS0 * 4;
#pragma unroll
        for (int f = t; f < 512; f += 256) {
            int r = f & 63, c4 = f >> 6;
            CP_ASYNC16(kdst + (r * STR + c4 * 4) * 4, kg + (size_t)r * DA + c4 * 8);
        }
        const __nv_bfloat16* vg = vgb;
        uint32_t vdst = smb + OVS0 * 4;
#pragma unroll
        for (int f = t; f < 2048; f += 256) {
            int c = f & 255, c4 = f >> 8;
            CP_ASYNC16(vdst + (c * STR + c4 * 4) * 4, vg + (size_t)c * NN + c4 * 8);
        }
        CP_COMMIT();
    }

    for (int jt = 0; jt < NN / TJ; jt++) {
        const int cur = jt & 1;
        __syncthreads();   // prev PV done: safe to refill other buffer & rewrite ps

        // ---- issue next tile's loads into the other buffer ----
        if (jt + 1 < NN / TJ) {
            const int j0n = (jt + 1) * TJ;
            const __nv_bfloat16* kg = kgb + (size_t)j0n * DA;
            uint32_t kdst = smb + (cur ? OKS0 : OKS1) * 4;
#pragma unroll
            for (int f = t; f < 512; f += 256) {
                int r = f & 63, c4 = f >> 6;
                CP_ASYNC16(kdst + (r * STR + c4 * 4) * 4, kg + (size_t)r * DA + c4 * 8);
            }
            const __nv_bfloat16* vg = vgb + j0n;
            uint32_t vdst = smb + (cur ? OVS0 : OVS1) * 4;
#pragma unroll
            for (int f = t; f < 2048; f += 256) {
                int c = f & 255, c4 = f >> 8;
                CP_ASYNC16(vdst + (c * STR + c4 * 4) * 4, vg + (size_t)c * NN + c4 * 8);
            }
            CP_COMMIT();
            CP_WAIT(1);    // current tile's group complete
        } else {
            CP_WAIT(0);
        }
        __syncthreads();   // staged data visible to all warps

        const uint32_t* ks = sm + (cur ? OKS1 : OKS0);
        const uint32_t* vs = sm + (cur ? OVS1 : OVS0);
        uint32_t* ps = sm + OPS;

        // ---- S = Q K^T : rows wr*16..+15, cols wc*32..+31 ----
        float sf[4][4];
#pragma unroll
        for (int n = 0; n < 4; n++)
#pragma unroll
            for (int r = 0; r < 4; r++) sf[n][r] = 0.f;
#pragma unroll
        for (int s = 0; s < 4; s++) {
#pragma unroll
            for (int n = 0; n < 4; n++) {
                const uint32_t* kb = &ks[(wc * 32 + n * 8 + g) * STR + s * 8 + tg];
                MMA_BF16(sf[n][0], sf[n][1], sf[n][2], sf[n][3],
                         qa[s][0], qa[s][1], qa[s][2], qa[s][3], kb[0], kb[4]);
            }
        }

        // ---- exp + P (bf16x2) + partial row sums ----
#pragma unroll
        for (int n = 0; n < 4; n++) {
            float p0, p1, p2, p3;
            asm("ex2.approx.ftz.f32 %0, %1;" : "=f"(p0) : "f"(sf[n][0]));
            asm("ex2.approx.ftz.f32 %0, %1;" : "=f"(p1) : "f"(sf[n][1]));
            asm("ex2.approx.ftz.f32 %0, %1;" : "=f"(p2) : "f"(sf[n][2]));
            asm("ex2.approx.ftz.f32 %0, %1;" : "=f"(p3) : "f"(sf[n][3]));
            l0 += p0 + p1;
            l1 += p2 + p3;
            int colw = wc * 16 + n * 4 + tg;
            uint32_t pk0, pk1;
            PACK_BF16X2(pk0, p0, p1);
            PACK_BF16X2(pk1, p2, p3);
            ps[(wr * 16 + g    ) * STR + colw] = pk0;
            ps[(wr * 16 + g + 8) * STR + colw] = pk1;
        }
        __syncthreads();

        // ---- O += P V : rows rg2*32..+31 (2 blocks), cols cg2*64..+63 ----
#pragma unroll
        for (int s = 0; s < 4; s++) {
            uint32_t a[2][4];
#pragma unroll
            for (int blk = 0; blk < 2; blk++) {
                const uint32_t* pr = &ps[(rg2 * 32 + blk * 16 + g) * STR + s * 8 + tg];
                a[blk][0] = pr[0];
                a[blk][2] = pr[4];
                a[blk][1] = pr[8 * STR];
                a[blk][3] = pr[8 * STR + 4];
            }
#pragma unroll
            for (int n = 0; n < 8; n++) {
                const uint32_t* vb = &vs[(cg2 * 64 + n * 8 + g) * STR + s * 8 + tg];
                uint32_t b0 = vb[0], b1 = vb[4];
                MMA_BF16(o[0][n][0], o[0][n][1], o[0][n][2], o[0][n][3],
                         a[0][0], a[0][1], a[0][2], a[0][3], b0, b1);
                MMA_BF16(o[1][n][0], o[1][n][1], o[1][n][2], o[1][n][3],
                         a[1][0], a[1][1], a[1][2], a[1][3], b0, b1);
            }
        }
    }

    // ---- reduce l across the two wc S-halves ----
    float* lsum = (float*)(sm + OLS);
    l0 += __shfl_xor_sync(0xffffffffu, l0, 1);
    l0 += __shfl_xor_sync(0xffffffffu, l0, 2);
    l1 += __shfl_xor_sync(0xffffffffu, l1, 1);
    l1 += __shfl_xor_sync(0xffffffffu, l1, 2);
    __syncthreads();
    if (tg == 0) {
        lsum[wc * 64 + wr * 16 + g    ] = l0;
        lsum[wc * 64 + wr * 16 + g + 8] = l1;
    }
    __syncthreads();

    // ---- epilogue: out[b][c][i] = O/l + x ----
#pragma unroll
    for (int blk = 0; blk < 2; blk++) {
        int rlo = rg2 * 32 + blk * 16 + g;
        const float linv0 = 1.0f / (lsum[rlo    ] + lsum[64 + rlo    ]);
        const float linv1 = 1.0f / (lsum[rlo + 8] + lsum[64 + rlo + 8]);
        const int r0 = i0 + rlo;
#pragma unroll
        for (int n = 0; n < 8; n++) {
            int c = cg2 * 64 + n * 8 + 2 * tg;
            size_t b0i = ((size_t)b * CC + c) * NN;
            size_t b1i = ((size_t)b * CC + c + 1) * NN;
            out[b0i + r0]     = fmaf(o[blk][n][0], linv0, x[b0i + r0]);
            out[b1i + r0]     = fmaf(o[blk][n][1], linv0, x[b1i + r0]);
            out[b0i + r0 + 8] = fmaf(o[blk][n][2], linv1, x[b0i + r0 + 8]);
            out[b1i + r0 + 8] = fmaf(o[blk][n][3], linv1, x[b1i + r0 + 8]);
        }
    }
}

// ---------------------------------------------------------------------------
extern "C" void kernel_launch(void* const* d_in, const int* in_sizes, int n_in,
                              void* d_out, int out_size)
{
    const float* x  = (const float*)d_in[0];
    const float* Wq = (const float*)d_in[1];
    const float* bq = (const float*)d_in[2];
    const float* Wk = (const float*)d_in[3];
    const float* bk = (const float*)d_in[4];
    const float* Wv = (const float*)d_in[5];
    const float* bv = (const float*)d_in[6];
    float* out = (float*)d_out;

    const int smem_bytes = SMW * 4;   // ~102 KB
    cudaFuncSetAttribute(attn_kernel, cudaFuncAttributeMaxDynamicSharedMemorySize, smem_bytes);

    proj_kernel<<<dim3(64, 3, BB), 256>>>(x, Wq, bq, Wk, bk, Wv, bv);
    attn_kernel<<<dim3(NN / TI, BB), 256, smem_bytes>>>(x, out);
}

// round 8
// speedup vs baseline: 7.6222x; 1.0296x over previous
#include <cuda_runtime.h>
#include <cuda_bf16.h>
#include <cstdint>

#define BB 16
#define CC 256
#define NN 4096
#define DA 64
#define TI 64
#define TJ 64

typedef unsigned long long u64;

// packed fp32x2 ops (proj kernel)
#define F2FMA(d, a, b, c) asm("fma.rn.f32x2 %0, %1, %2, %3;" : "=l"(d) : "l"(a), "l"(b), "l"(c))
#define F2BCAST(d, s)     asm("mov.b64 %0, {%1, %1};" : "=l"(d) : "r"(__float_as_uint(s)))
#define F2UNPACK(lo, hi, v) asm("mov.b64 {%0, %1}, %2;" : "=f"(lo), "=f"(hi) : "l"(v))

#define MMA_BF16(d0,d1,d2,d3,a0,a1,a2,a3,b0,b1) \
    asm volatile("mma.sync.aligned.m16n8k16.row.col.f32.bf16.bf16.f32 " \
        "{%0,%1,%2,%3}, {%4,%5,%6,%7}, {%8,%9}, {%0,%1,%2,%3};" \
        : "+f"(d0), "+f"(d1), "+f"(d2), "+f"(d3) \
        : "r"(a0), "r"(a1), "r"(a2), "r"(a3), "r"(b0), "r"(b1))

#define PACK_BF16X2(d, lo, hi) \
    asm("cvt.rn.bf16x2.f32 %0, %1, %2;" : "=r"(d) : "f"(hi), "f"(lo))

#define LDSM_X4(r0,r1,r2,r3, addr) \
    asm volatile("ldmatrix.sync.aligned.m8n8.x4.shared.b16 {%0,%1,%2,%3}, [%4];" \
        : "=r"(r0), "=r"(r1), "=r"(r2), "=r"(r3) : "r"(addr))

// cp.async (sm_80+)
#define CP_ASYNC16(dst, src) \
    asm volatile("cp.async.cg.shared.global [%0], [%1], 16;" :: "r"(dst), "l"(src) : "memory")
#define CP_COMMIT() asm volatile("cp.async.commit_group;" ::: "memory")
#define CP_WAIT(n)  asm volatile("cp.async.wait_group %0;" :: "n"(n) : "memory")

// Scratch (bf16)
__device__ __nv_bfloat16 g_q[(size_t)BB * NN * DA];   // [b][n][a] (pre-scaled log2e/64)
__device__ __nv_bfloat16 g_k[(size_t)BB * NN * DA];   // [b][n][a]
__device__ __nv_bfloat16 g_v[(size_t)BB * CC * NN];   // [b][c][n] TRANSPOSED

// ---------------------------------------------------------------------------
// Kernel 1: fused QKV projection (FFMA2, fp32 math) -> bf16 outputs
// ---------------------------------------------------------------------------
__global__ __launch_bounds__(256) void proj_kernel(
    const float* __restrict__ x,
    const float* __restrict__ Wq, const float* __restrict__ bq,
    const float* __restrict__ Wk, const float* __restrict__ bk,
    const float* __restrict__ Wv, const float* __restrict__ bv)
{
    __shared__ float xs[64][64];
    __shared__ float ws[128][64];

    const int t  = threadIdx.x;
    const int nt = blockIdx.x;
    const int rg = blockIdx.y;
    const int b  = blockIdx.z;
    const int n0 = nt * 64;
    const int tn = t & 15;
    const int tr = t >> 4;

    u64 accp[8][2];
#pragma unroll
    for (int q = 0; q < 8; q++) { accp[q][0] = 0ull; accp[q][1] = 0ull; }

    for (int c0 = 0; c0 < CC; c0 += 64) {
        __syncthreads();
#pragma unroll
        for (int f = t; f < 64 * 16; f += 256) {
            int cc = f >> 4, n4 = f & 15;
            *(float4*)&xs[cc][n4 * 4] =
                *(const float4*)&x[((size_t)b * CC + (c0 + cc)) * NN + n0 + n4 * 4];
        }
#pragma unroll
        for (int f = t; f < 128 * 16; f += 256) {
            int r = f >> 4, c4 = f & 15;
            const float* wp;
            if (rg == 0) wp = (r < 64) ? (Wq + r * CC) : (Wk + (r - 64) * CC);
            else         wp = Wv + ((size_t)((rg - 1) * 128 + r)) * CC;
            *(float4*)&ws[r][c4 * 4] = *(const float4*)&wp[c0 + c4 * 4];
        }
        __syncthreads();
#pragma unroll 8
        for (int cc = 0; cc < 64; cc++) {
            ulonglong2 xp = *(ulonglong2*)&xs[cc][tn * 4];
#pragma unroll
            for (int q = 0; q < 8; q++) {
                u64 wpk; F2BCAST(wpk, ws[tr * 8 + q][cc]);
                F2FMA(accp[q][0], wpk, xp.x, accp[q][0]);
                F2FMA(accp[q][1], wpk, xp.y, accp[q][1]);
            }
        }
    }

    float acc[8][4];
#pragma unroll
    for (int q = 0; q < 8; q++) {
        F2UNPACK(acc[q][0], acc[q][1], accp[q][0]);
        F2UNPACK(acc[q][2], acc[q][3], accp[q][1]);
    }

    const float qscale = 1.4426950408889634f / 64.0f;  // log2(e)/sqrt(N)
#pragma unroll
    for (int q = 0; q < 8; q++) {
        int r = tr * 8 + q;
        if (rg == 0) {
            if (r < 64) {
                float bias = bq[r];
                __nv_bfloat16* dst = g_q + (size_t)b * NN * DA;
#pragma unroll
                for (int j = 0; j < 4; j++) {
                    int n = n0 + tn * 4 + j;
                    dst[(size_t)n * DA + r] = __float2bfloat16((acc[q][j] + bias) * qscale);
                }
            } else {
                float bias = bk[r - 64];
                __nv_bfloat16* dst = g_k + (size_t)b * NN * DA;
#pragma unroll
                for (int j = 0; j < 4; j++) {
                    int n = n0 + tn * 4 + j;
                    dst[(size_t)n * DA + (r - 64)] = __float2bfloat16(acc[q][j] + bias);
                }
            }
        } else {
            int c = (rg - 1) * 128 + r;
            float bias = bv[c];
            uint2 st;
            PACK_BF16X2(st.x, acc[q][0] + bias, acc[q][1] + bias);
            PACK_BF16X2(st.y, acc[q][2] + bias, acc[q][3] + bias);
            *(uint2*)&g_v[((size_t)b * CC + c) * NN + n0 + tn * 4] = st;
        }
    }
}

// ---------------------------------------------------------------------------
// Kernel 2: bf16 mma.sync flash attention; ldmatrix operand loads;
// cp.async double-buffered; 2 CTA/SM.
// ---------------------------------------------------------------------------
#define STR 36           // row stride (words): conflict-free everywhere
#define KW  (TJ * STR)
#define VW  (CC * STR)
#define OKS0 0
#define OVS0 (OKS0 + KW)
#define OKS1 (OVS0 + VW)
#define OVS1 (OKS1 + KW)
#define OPS  (OVS1 + VW)
#define OLS  (OPS + TI * STR)
#define SMW  (OLS + 2 * 64)

__device__ __forceinline__ uint32_t smem_u32(const void* p) {
    uint32_t a;
    asm("{ .reg .u64 t; cvta.to.shared.u64 t, %1; cvt.u32.u64 %0, t; }" : "=r"(a) : "l"(p));
    return a;
}

__global__ __launch_bounds__(256, 2) void attn_kernel(
    const float* __restrict__ x, float* __restrict__ out)
{
    extern __shared__ __align__(16) uint32_t sm[];
    const uint32_t smb = smem_u32(sm);

    const int t    = threadIdx.x;
    const int lane = t & 31;
    const int wid  = t >> 5;
    const int g    = lane >> 2;
    const int tg   = lane & 3;
    const int wr   = wid & 3;      // S rows: wr*16
    const int wc   = wid >> 2;     // S cols: wc*32
    const int rg2  = wid & 1;      // PV rows: rg2*32
    const int cg2  = wid >> 1;     // PV cols: cg2*64
    const int b    = blockIdx.y;
    const int i0   = blockIdx.x * TI;

    // ldmatrix lane decomposition
    const int lrow = lane & 7;
    const int q8   = lane >> 3;          // quad 0..3
    const int bqr  = q8 >> 1, bqc = q8 & 1;   // B-frag: m0/m1 = k-halves, m2/m3 = +8 rows
    const int aqr  = q8 & 1,  aqc = q8 >> 1;  // A-frag: m0/m1 = rows, m2/m3 = k-halves

    // per-thread ldmatrix base addresses (byte offsets into sm)
    const uint32_t kbase = smb + 4 * ((wc * 32 + bqr * 8 + lrow) * STR + bqc * 4);
    const uint32_t vbase = smb + 4 * (OVS0 * 0 + (cg2 * 64 + bqr * 8 + lrow) * STR + bqc * 4);
    const uint32_t pbase = smb + 4 * (OPS + (rg2 * 32 + aqr * 8 + lrow) * STR + aqc * 4);

    // ---- Q fragments in registers (4 k16-steps), loaded once ----
    uint32_t qa[4][4];
    {
        const __nv_bfloat16* qg = g_q + ((size_t)b * NN + i0 + wr * 16) * DA;
#pragma unroll
        for (int s = 0; s < 4; s++) {
            qa[s][0] = *(const uint32_t*)&qg[(size_t)(g    ) * DA + s * 16 + 2 * tg    ];
            qa[s][1] = *(const uint32_t*)&qg[(size_t)(g + 8) * DA + s * 16 + 2 * tg    ];
            qa[s][2] = *(const uint32_t*)&qg[(size_t)(g    ) * DA + s * 16 + 2 * tg + 8];
            qa[s][3] = *(const uint32_t*)&qg[(size_t)(g + 8) * DA + s * 16 + 2 * tg + 8];
        }
    }

    float o[2][8][4];
#pragma unroll
    for (int blk = 0; blk < 2; blk++)
#pragma unroll
        for (int n = 0; n < 8; n++)
#pragma unroll
            for (int r = 0; r < 4; r++) o[blk][n][r] = 0.f;

    float l0 = 0.f, l1 = 0.f;

    const __nv_bfloat16* kgb = g_k + (size_t)b * NN * DA;
    const __nv_bfloat16* vgb = g_v + (size_t)b * CC * NN;

    // ---- prologue: stage tile 0 into buffer 0 ----
    {
        uint32_t kdst = smb + OKS0 * 4;
#pragma unroll
        for (int f = t; f < 512; f += 256) {
            int r = f & 63, c4 = f >> 6;
            CP_ASYNC16(kdst + (r * STR + c4 * 4) * 4, kgb + (size_t)r * DA + c4 * 8);
        }
        uint32_t vdst = smb + OVS0 * 4;
#pragma unroll
        for (int f = t; f < 2048; f += 256) {
            int c = f & 255, c4 = f >> 8;
            CP_ASYNC16(vdst + (c * STR + c4 * 4) * 4, vgb + (size_t)c * NN + c4 * 8);
        }
        CP_COMMIT();
    }

    for (int jt = 0; jt < NN / TJ; jt++) {
        const int cur = jt & 1;
        __syncthreads();

        if (jt + 1 < NN / TJ) {
            const int j0n = (jt + 1) * TJ;
            const __nv_bfloat16* kg = kgb + (size_t)j0n * DA;
            uint32_t kdst = smb + (cur ? OKS0 : OKS1) * 4;
#pragma unroll
            for (int f = t; f < 512; f += 256) {
                int r = f & 63, c4 = f >> 6;
                CP_ASYNC16(kdst + (r * STR + c4 * 4) * 4, kg + (size_t)r * DA + c4 * 8);
            }
            const __nv_bfloat16* vg = vgb + j0n;
            uint32_t vdst = smb + (cur ? OVS0 : OVS1) * 4;
#pragma unroll
            for (int f = t; f < 2048; f += 256) {
                int c = f & 255, c4 = f >> 8;
                CP_ASYNC16(vdst + (c * STR + c4 * 4) * 4, vg + (size_t)c * NN + c4 * 8);
            }
            CP_COMMIT();
            CP_WAIT(1);
        } else {
            CP_WAIT(0);
        }
        __syncthreads();

        const uint32_t koff = (cur ? OKS1 : OKS0) * 4;
        const uint32_t voff = (cur ? OVS1 : OVS0) * 4;
        uint32_t* ps = sm + OPS;

        // ---- S = Q K^T : rows wr*16..+15, cols wc*32..+31 ----
        float sf[4][4];
#pragma unroll
        for (int n = 0; n < 4; n++)
#pragma unroll
            for (int r = 0; r < 4; r++) sf[n][r] = 0.f;
#pragma unroll
        for (int s = 0; s < 4; s++) {
#pragma unroll
            for (int nbp = 0; nbp < 2; nbp++) {   // covers n-blocks 2*nbp, 2*nbp+1
                uint32_t b0, b1, b2, b3;
                LDSM_X4(b0, b1, b2, b3, kbase + koff + 4 * (nbp * 16 * STR + s * 8));
                MMA_BF16(sf[nbp*2][0], sf[nbp*2][1], sf[nbp*2][2], sf[nbp*2][3],
                         qa[s][0], qa[s][1], qa[s][2], qa[s][3], b0, b1);
                MMA_BF16(sf[nbp*2+1][0], sf[nbp*2+1][1], sf[nbp*2+1][2], sf[nbp*2+1][3],
                         qa[s][0], qa[s][1], qa[s][2], qa[s][3], b2, b3);
            }
        }

        // ---- exp + P (bf16x2) + partial row sums ----
#pragma unroll
        for (int n = 0; n < 4; n++) {
            float p0, p1, p2, p3;
            asm("ex2.approx.ftz.f32 %0, %1;" : "=f"(p0) : "f"(sf[n][0]));
            asm("ex2.approx.ftz.f32 %0, %1;" : "=f"(p1) : "f"(sf[n][1]));
            asm("ex2.approx.ftz.f32 %0, %1;" : "=f"(p2) : "f"(sf[n][2]));
            asm("ex2.approx.ftz.f32 %0, %1;" : "=f"(p3) : "f"(sf[n][3]));
            l0 += p0 + p1;
            l1 += p2 + p3;
            int colw = wc * 16 + n * 4 + tg;
            uint32_t pk0, pk1;
            PACK_BF16X2(pk0, p0, p1);
            PACK_BF16X2(pk1, p2, p3);
            ps[(wr * 16 + g    ) * STR + colw] = pk0;
            ps[(wr * 16 + g + 8) * STR + colw] = pk1;
        }
        __syncthreads();

        // ---- O += P V : rows rg2*32..+31 (2 blocks of 16), cols cg2*64..+63 ----
#pragma unroll
        for (int s = 0; s < 4; s++) {
            uint32_t a[2][4];
#pragma unroll
            for (int blk = 0; blk < 2; blk++) {
                LDSM_X4(a[blk][0], a[blk][1], a[blk][2], a[blk][3],
                        pbase + 4 * (blk * 16 * STR + s * 8));
            }
#pragma unroll
            for (int nbp = 0; nbp < 4; nbp++) {   // covers n-blocks 2*nbp, 2*nbp+1
                uint32_t b0, b1, b2, b3;
                LDSM_X4(b0, b1, b2, b3, vbase + voff + 4 * (nbp * 16 * STR + s * 8));
                MMA_BF16(o[0][nbp*2][0], o[0][nbp*2][1], o[0][nbp*2][2], o[0][nbp*2][3],
                         a[0][0], a[0][1], a[0][2], a[0][3], b0, b1);
                MMA_BF16(o[1][nbp*2][0], o[1][nbp*2][1], o[1][nbp*2][2], o[1][nbp*2][3],
                         a[1][0], a[1][1], a[1][2], a[1][3], b0, b1);
                MMA_BF16(o[0][nbp*2+1][0], o[0][nbp*2+1][1], o[0][nbp*2+1][2], o[0][nbp*2+1][3],
                         a[0][0], a[0][1], a[0][2], a[0][3], b2, b3);
                MMA_BF16(o[1][nbp*2+1][0], o[1][nbp*2+1][1], o[1][nbp*2+1][2], o[1][nbp*2+1][3],
                         a[1][0], a[1][1], a[1][2], a[1][3], b2, b3);
            }
        }
    }

    // ---- reduce l across the two wc S-halves ----
    float* lsum = (float*)(sm + OLS);
    l0 += __shfl_xor_sync(0xffffffffu, l0, 1);
    l0 += __shfl_xor_sync(0xffffffffu, l0, 2);
    l1 += __shfl_xor_sync(0xffffffffu, l1, 1);
    l1 += __shfl_xor_sync(0xffffffffu, l1, 2);
    __syncthreads();
    if (tg == 0) {
        lsum[wc * 64 + wr * 16 + g    ] = l0;
        lsum[wc * 64 + wr * 16 + g + 8] = l1;
    }
    __syncthreads();

    // ---- epilogue: out[b][c][i] = O/l + x ----
#pragma unroll
    for (int blk = 0; blk < 2; blk++) {
        int rlo = rg2 * 32 + blk * 16 + g;
        const float linv0 = 1.0f / (lsum[rlo    ] + lsum[64 + rlo    ]);
        const float linv1 = 1.0f / (lsum[rlo + 8] + lsum[64 + rlo + 8]);
        const int r0 = i0 + rlo;
#pragma unroll
        for (int n = 0; n < 8; n++) {
            int c = cg2 * 64 + n * 8 + 2 * tg;
            size_t b0i = ((size_t)b * CC + c) * NN;
            size_t b1i = ((size_t)b * CC + c + 1) * NN;
            out[b0i + r0]     = fmaf(o[blk][n][0], linv0, x[b0i + r0]);
            out[b1i + r0]     = fmaf(o[blk][n][1], linv0, x[b1i + r0]);
            out[b0i + r0 + 8] = fmaf(o[blk][n][2], linv1, x[b0i + r0 + 8]);
            out[b1i + r0 + 8] = fmaf(o[blk][n][3], linv1, x[b1i + r0 + 8]);
        }
    }
}

// ---------------------------------------------------------------------------
extern "C" void kernel_launch(void* const* d_in, const int* in_sizes, int n_in,
                              void* d_out, int out_size)
{
    const float* x  = (const float*)d_in[0];
    const float* Wq = (const float*)d_in[1];
    const float* bq = (const float*)d_in[2];
    const float* Wk = (const float*)d_in[3];
    const float* bk = (const float*)d_in[4];
    const float* Wv = (const float*)d_in[5];
    const float* bv = (const float*)d_in[6];
    float* out = (float*)d_out;

    const int smem_bytes = SMW * 4;   // ~102 KB
    cudaFuncSetAttribute(attn_kernel, cudaFuncAttributeMaxDynamicSharedMemorySize, smem_bytes);

    proj_kernel<<<dim3(64, 3, BB), 256>>>(x, Wq, bq, Wk, bk, Wv, bv);
    attn_kernel<<<dim3(NN / TI, BB), 256, smem_bytes>>>(x, out);
}

// round 9
// speedup vs baseline: 8.7095x; 1.1427x over previous
#include <cuda_runtime.h>
#include <cuda_bf16.h>
#include <cstdint>

#define BB 16
#define CC 256
#define NN 4096
#define DA 64
#define TI 128
#define TJ 64

typedef unsigned long long u64;

// packed fp32x2 ops (proj kernel)
#define F2FMA(d, a, b, c) asm("fma.rn.f32x2 %0, %1, %2, %3;" : "=l"(d) : "l"(a), "l"(b), "l"(c))
#define F2BCAST(d, s)     asm("mov.b64 %0, {%1, %1};" : "=l"(d) : "r"(__float_as_uint(s)))
#define F2UNPACK(lo, hi, v) asm("mov.b64 {%0, %1}, %2;" : "=f"(lo), "=f"(hi) : "l"(v))

#define MMA_BF16(d0,d1,d2,d3,a0,a1,a2,a3,b0,b1) \
    asm volatile("mma.sync.aligned.m16n8k16.row.col.f32.bf16.bf16.f32 " \
        "{%0,%1,%2,%3}, {%4,%5,%6,%7}, {%8,%9}, {%0,%1,%2,%3};" \
        : "+f"(d0), "+f"(d1), "+f"(d2), "+f"(d3) \
        : "r"(a0), "r"(a1), "r"(a2), "r"(a3), "r"(b0), "r"(b1))

#define PACK_BF16X2(d, lo, hi) \
    asm("cvt.rn.bf16x2.f32 %0, %1, %2;" : "=r"(d) : "f"(hi), "f"(lo))

#define LDSM_X4(r0,r1,r2,r3, addr) \
    asm volatile("ldmatrix.sync.aligned.m8n8.x4.shared.b16 {%0,%1,%2,%3}, [%4];" \
        : "=r"(r0), "=r"(r1), "=r"(r2), "=r"(r3) : "r"(addr))

// cp.async (sm_80+)
#define CP_ASYNC16(dst, src) \
    asm volatile("cp.async.cg.shared.global [%0], [%1], 16;" :: "r"(dst), "l"(src) : "memory")
#define CP_COMMIT() asm volatile("cp.async.commit_group;" ::: "memory")
#define CP_WAIT(n)  asm volatile("cp.async.wait_group %0;" :: "n"(n) : "memory")

// Scratch (bf16)
__device__ __nv_bfloat16 g_q[(size_t)BB * NN * DA];   // [b][n][a] (pre-scaled log2e/64)
__device__ __nv_bfloat16 g_k[(size_t)BB * NN * DA];   // [b][n][a]
__device__ __nv_bfloat16 g_v[(size_t)BB * CC * NN];   // [b][c][n] TRANSPOSED

// ---------------------------------------------------------------------------
// Kernel 1: fused QKV projection (FFMA2, fp32 math) -> bf16 outputs
// ---------------------------------------------------------------------------
__global__ __launch_bounds__(256) void proj_kernel(
    const float* __restrict__ x,
    const float* __restrict__ Wq, const float* __restrict__ bq,
    const float* __restrict__ Wk, const float* __restrict__ bk,
    const float* __restrict__ Wv, const float* __restrict__ bv)
{
    __shared__ float xs[64][64];
    __shared__ float ws[128][64];

    const int t  = threadIdx.x;
    const int nt = blockIdx.x;
    const int rg = blockIdx.y;
    const int b  = blockIdx.z;
    const int n0 = nt * 64;
    const int tn = t & 15;
    const int tr = t >> 4;

    u64 accp[8][2];
#pragma unroll
    for (int q = 0; q < 8; q++) { accp[q][0] = 0ull; accp[q][1] = 0ull; }

    for (int c0 = 0; c0 < CC; c0 += 64) {
        __syncthreads();
#pragma unroll
        for (int f = t; f < 64 * 16; f += 256) {
            int cc = f >> 4, n4 = f & 15;
            *(float4*)&xs[cc][n4 * 4] =
                *(const float4*)&x[((size_t)b * CC + (c0 + cc)) * NN + n0 + n4 * 4];
        }
#pragma unroll
        for (int f = t; f < 128 * 16; f += 256) {
            int r = f >> 4, c4 = f & 15;
            const float* wp;
            if (rg == 0) wp = (r < 64) ? (Wq + r * CC) : (Wk + (r - 64) * CC);
            else         wp = Wv + ((size_t)((rg - 1) * 128 + r)) * CC;
            *(float4*)&ws[r][c4 * 4] = *(const float4*)&wp[c0 + c4 * 4];
        }
        __syncthreads();
#pragma unroll 8
        for (int cc = 0; cc < 64; cc++) {
            ulonglong2 xp = *(ulonglong2*)&xs[cc][tn * 4];
#pragma unroll
            for (int q = 0; q < 8; q++) {
                u64 wpk; F2BCAST(wpk, ws[tr * 8 + q][cc]);
                F2FMA(accp[q][0], wpk, xp.x, accp[q][0]);
                F2FMA(accp[q][1], wpk, xp.y, accp[q][1]);
            }
        }
    }

    float acc[8][4];
#pragma unroll
    for (int q = 0; q < 8; q++) {
        F2UNPACK(acc[q][0], acc[q][1], accp[q][0]);
        F2UNPACK(acc[q][2], acc[q][3], accp[q][1]);
    }

    const float qscale = 1.4426950408889634f / 64.0f;  // log2(e)/sqrt(N)
#pragma unroll
    for (int q = 0; q < 8; q++) {
        int r = tr * 8 + q;
        if (rg == 0) {
            if (r < 64) {
                float bias = bq[r];
                __nv_bfloat16* dst = g_q + (size_t)b * NN * DA;
#pragma unroll
                for (int j = 0; j < 4; j++) {
                    int n = n0 + tn * 4 + j;
                    dst[(size_t)n * DA + r] = __float2bfloat16((acc[q][j] + bias) * qscale);
                }
            } else {
                float bias = bk[r - 64];
                __nv_bfloat16* dst = g_k + (size_t)b * NN * DA;
#pragma unroll
                for (int j = 0; j < 4; j++) {
                    int n = n0 + tn * 4 + j;
                    dst[(size_t)n * DA + (r - 64)] = __float2bfloat16(acc[q][j] + bias);
                }
            }
        } else {
            int c = (rg - 1) * 128 + r;
            float bias = bv[c];
            uint2 st;
            PACK_BF16X2(st.x, acc[q][0] + bias, acc[q][1] + bias);
            PACK_BF16X2(st.y, acc[q][2] + bias, acc[q][3] + bias);
            *(uint2*)&g_v[((size_t)b * CC + c) * NN + n0 + tn * 4] = st;
        }
    }
}

// ---------------------------------------------------------------------------
// Kernel 2: bf16 mma.sync flash attention, P-in-registers (FA2 layout
// identity), TI=128, 8 warps x 16 rows, full j+c per warp, 2 barriers/tile.
// ---------------------------------------------------------------------------
#define STR 36
#define KW  (TJ * STR)    // 2304 words
#define VW  (CC * STR)    // 9216 words
#define OKS0 0
#define OVS0 KW
#define OKS1 (KW + VW)
#define OVS1 (2 * KW + VW)
#define SMW  (2 * (KW + VW))   // 23040 words = 92 KB

__device__ __forceinline__ uint32_t smem_u32(const void* p) {
    uint32_t a;
    asm("{ .reg .u64 t; cvta.to.shared.u64 t, %1; cvt.u32.u64 %0, t; }" : "=r"(a) : "l"(p));
    return a;
}

__global__ __launch_bounds__(256, 1) void attn_kernel(
    const float* __restrict__ x, float* __restrict__ out)
{
    extern __shared__ __align__(16) uint32_t sm[];
    const uint32_t smb = smem_u32(sm);

    const int t    = threadIdx.x;
    const int lane = t & 31;
    const int wid  = t >> 5;       // 8 warps: rows wid*16 .. +15
    const int g    = lane >> 2;
    const int tg   = lane & 3;
    const int b    = blockIdx.y;
    const int i0   = blockIdx.x * TI;

    // ldmatrix lane decomposition (B-fragments for K and V)
    const int lrow = lane & 7;
    const int q8   = lane >> 3;
    const int bqr  = q8 >> 1, bqc = q8 & 1;
    const uint32_t rowpart = 4 * ((bqr * 8 + lrow) * STR + bqc * 4);

    // ---- Q fragments in registers (4 k16-steps), loaded once ----
    uint32_t qa[4][4];
    {
        const __nv_bfloat16* qg = g_q + ((size_t)b * NN + i0 + wid * 16) * DA;
#pragma unroll
        for (int s = 0; s < 4; s++) {
            qa[s][0] = *(const uint32_t*)&qg[(size_t)(g    ) * DA + s * 16 + 2 * tg    ];
            qa[s][1] = *(const uint32_t*)&qg[(size_t)(g + 8) * DA + s * 16 + 2 * tg    ];
            qa[s][2] = *(const uint32_t*)&qg[(size_t)(g    ) * DA + s * 16 + 2 * tg + 8];
            qa[s][3] = *(const uint32_t*)&qg[(size_t)(g + 8) * DA + s * 16 + 2 * tg + 8];
        }
    }

    float o[32][4];
#pragma unroll
    for (int n = 0; n < 32; n++)
#pragma unroll
        for (int r = 0; r < 4; r++) o[n][r] = 0.f;

    float l0 = 0.f, l1 = 0.f;

    const __nv_bfloat16* kgb = g_k + (size_t)b * NN * DA;
    const __nv_bfloat16* vgb = g_v + (size_t)b * CC * NN;

    // ---- prologue: stage tile 0 into buffer 0 ----
    {
        uint32_t kdst = smb + OKS0 * 4;
#pragma unroll
        for (int f = t; f < 512; f += 256) {
            int r = f & 63, c4 = f >> 6;
            CP_ASYNC16(kdst + (r * STR + c4 * 4) * 4, kgb + (size_t)r * DA + c4 * 8);
        }
        uint32_t vdst = smb + OVS0 * 4;
#pragma unroll
        for (int f = t; f < 2048; f += 256) {
            int c = f & 255, c4 = f >> 8;
            CP_ASYNC16(vdst + (c * STR + c4 * 4) * 4, vgb + (size_t)c * NN + c4 * 8);
        }
        CP_COMMIT();
    }

    for (int jt = 0; jt < NN / TJ; jt++) {
        const int cur = jt & 1;
        __syncthreads();   // all warps done reading buffer (1-cur) from tile jt-1

        if (jt + 1 < NN / TJ) {
            const int j0n = (jt + 1) * TJ;
            const __nv_bfloat16* kg = kgb + (size_t)j0n * DA;
            uint32_t kdst = smb + (cur ? OKS0 : OKS1) * 4;
#pragma unroll
            for (int f = t; f < 512; f += 256) {
                int r = f & 63, c4 = f >> 6;
                CP_ASYNC16(kdst + (r * STR + c4 * 4) * 4, kg + (size_t)r * DA + c4 * 8);
            }
            const __nv_bfloat16* vg = vgb + j0n;
            uint32_t vdst = smb + (cur ? OVS0 : OVS1) * 4;
#pragma unroll
            for (int f = t; f < 2048; f += 256) {
                int c = f & 255, c4 = f >> 8;
                CP_ASYNC16(vdst + (c * STR + c4 * 4) * 4, vg + (size_t)c * NN + c4 * 8);
            }
            CP_COMMIT();
            CP_WAIT(1);    // tile jt's group complete
        } else {
            CP_WAIT(0);
        }
        __syncthreads();   // staged data visible to all warps

        const uint32_t kbase = smb + (cur ? OKS1 : OKS0) * 4 + rowpart;
        const uint32_t vbase = smb + (cur ? OVS1 : OVS0) * 4 + rowpart;

        // ---- S = Q K^T : rows wid*16..+15, full j (8 n-blocks) ----
        float sf[8][4];
#pragma unroll
        for (int n = 0; n < 8; n++)
#pragma unroll
            for (int r = 0; r < 4; r++) sf[n][r] = 0.f;
#pragma unroll
        for (int s = 0; s < 4; s++) {
#pragma unroll
            for (int nbp = 0; nbp < 4; nbp++) {
                uint32_t b0, b1, b2, b3;
                LDSM_X4(b0, b1, b2, b3, kbase + 4 * (nbp * 16 * STR + s * 8));
                MMA_BF16(sf[nbp*2][0], sf[nbp*2][1], sf[nbp*2][2], sf[nbp*2][3],
                         qa[s][0], qa[s][1], qa[s][2], qa[s][3], b0, b1);
                MMA_BF16(sf[nbp*2+1][0], sf[nbp*2+1][1], sf[nbp*2+1][2], sf[nbp*2+1][3],
                         qa[s][0], qa[s][1], qa[s][2], qa[s][3], b2, b3);
            }
        }

        // ---- exp + pack P directly into A-fragments (no smem round-trip) ----
        uint32_t pa[4][4];
#pragma unroll
        for (int nb = 0; nb < 8; nb++) {
            float e0, e1, e2, e3;
            asm("ex2.approx.ftz.f32 %0, %1;" : "=f"(e0) : "f"(sf[nb][0]));
            asm("ex2.approx.ftz.f32 %0, %1;" : "=f"(e1) : "f"(sf[nb][1]));
            asm("ex2.approx.ftz.f32 %0, %1;" : "=f"(e2) : "f"(sf[nb][2]));
            asm("ex2.approx.ftz.f32 %0, %1;" : "=f"(e3) : "f"(sf[nb][3]));
            l0 += e0 + e1;
            l1 += e2 + e3;
            int s = nb >> 1, hi = (nb & 1) * 2;
            PACK_BF16X2(pa[s][hi    ], e0, e1);
            PACK_BF16X2(pa[s][hi + 1], e2, e3);
        }

        // ---- O += P V : rows wid*16..+15, full c (32 n-blocks) ----
#pragma unroll
        for (int s = 0; s < 4; s++) {
#pragma unroll
            for (int nbp = 0; nbp < 16; nbp++) {
                uint32_t b0, b1, b2, b3;
                LDSM_X4(b0, b1, b2, b3, vbase + 4 * (nbp * 16 * STR + s * 8));
                MMA_BF16(o[nbp*2][0], o[nbp*2][1], o[nbp*2][2], o[nbp*2][3],
                         pa[s][0], pa[s][1], pa[s][2], pa[s][3], b0, b1);
                MMA_BF16(o[nbp*2+1][0], o[nbp*2+1][1], o[nbp*2+1][2], o[nbp*2+1][3],
                         pa[s][0], pa[s][1], pa[s][2], pa[s][3], b2, b3);
            }
        }
    }

    // ---- l complete within warp (full j per warp): quad reduce ----
    l0 += __shfl_xor_sync(0xffffffffu, l0, 1);
    l0 += __shfl_xor_sync(0xffffffffu, l0, 2);
    l1 += __shfl_xor_sync(0xffffffffu, l1, 1);
    l1 += __shfl_xor_sync(0xffffffffu, l1, 2);
    const float linv0 = 1.0f / l0;
    const float linv1 = 1.0f / l1;

    // ---- epilogue: out[b][c][i] = O/l + x ----
    const int r0 = i0 + wid * 16 + g;
#pragma unroll
    for (int nb = 0; nb < 32; nb++) {
        int c = nb * 8 + 2 * tg;
        size_t b0i = ((size_t)b * CC + c) * NN;
        size_t b1i = ((size_t)b * CC + c + 1) * NN;
        out[b0i + r0]     = fmaf(o[nb][0], linv0, x[b0i + r0]);
        out[b1i + r0]     = fmaf(o[nb][1], linv0, x[b1i + r0]);
        out[b0i + r0 + 8] = fmaf(o[nb][2], linv1, x[b0i + r0 + 8]);
        out[b1i + r0 + 8] = fmaf(o[nb][3], linv1, x[b1i + r0 + 8]);
    }
}

// ---------------------------------------------------------------------------
extern "C" void kernel_launch(void* const* d_in, const int* in_sizes, int n_in,
                              void* d_out, int out_size)
{
    const float* x  = (const float*)d_in[0];
    const float* Wq = (const float*)d_in[1];
    const float* bq = (const float*)d_in[2];
    const float* Wk = (const float*)d_in[3];
    const float* bk = (const float*)d_in[4];
    const float* Wv = (const float*)d_in[5];
    const float* bv = (const float*)d_in[6];
    float* out = (float*)d_out;

    const int smem_bytes = SMW * 4;   // 92 KB
    cudaFuncSetAttribute(attn_kernel, cudaFuncAttributeMaxDynamicSharedMemorySize, smem_bytes);

    proj_kernel<<<dim3(64, 3, BB), 256>>>(x, Wq, bq, Wk, bk, Wv, bv);
    attn_kernel<<<dim3(NN / TI, BB), 256, smem_bytes>>>(x, out);
}

// round 10
// speedup vs baseline: 12.6018x; 1.4469x over previous
#include <cuda_runtime.h>
#include <cuda_bf16.h>
#include <cstdint>

#define BB 16
#define CC 256
#define NN 4096
#define DA 64
#define TI 128
#define TJ 64

typedef unsigned long long u64;

#define MMA_BF16(d0,d1,d2,d3,a0,a1,a2,a3,b0,b1) \
    asm volatile("mma.sync.aligned.m16n8k16.row.col.f32.bf16.bf16.f32 " \
        "{%0,%1,%2,%3}, {%4,%5,%6,%7}, {%8,%9}, {%0,%1,%2,%3};" \
        : "+f"(d0), "+f"(d1), "+f"(d2), "+f"(d3) \
        : "r"(a0), "r"(a1), "r"(a2), "r"(a3), "r"(b0), "r"(b1))

#define PACK_BF16X2(d, lo, hi) \
    asm("cvt.rn.bf16x2.f32 %0, %1, %2;" : "=r"(d) : "f"(hi), "f"(lo))

#define LDSM_X4(r0,r1,r2,r3, addr) \
    asm volatile("ldmatrix.sync.aligned.m8n8.x4.shared.b16 {%0,%1,%2,%3}, [%4];" \
        : "=r"(r0), "=r"(r1), "=r"(r2), "=r"(r3) : "r"(addr))

#define LDSM_T_X4(r0,r1,r2,r3, addr) \
    asm volatile("ldmatrix.sync.aligned.m8n8.x4.trans.shared.b16 {%0,%1,%2,%3}, [%4];" \
        : "=r"(r0), "=r"(r1), "=r"(r2), "=r"(r3) : "r"(addr))

// cp.async (sm_80+)
#define CP_ASYNC16(dst, src) \
    asm volatile("cp.async.cg.shared.global [%0], [%1], 16;" :: "r"(dst), "l"(src) : "memory")
#define CP_COMMIT() asm volatile("cp.async.commit_group;" ::: "memory")
#define CP_WAIT(n)  asm volatile("cp.async.wait_group %0;" :: "n"(n) : "memory")

// Scratch (bf16)
__device__ __nv_bfloat16 g_q[(size_t)BB * NN * DA];   // [b][n][a] (pre-scaled log2e/64)
__device__ __nv_bfloat16 g_k[(size_t)BB * NN * DA];   // [b][n][a]
__device__ __nv_bfloat16 g_v[(size_t)BB * CC * NN];   // [b][c][n] TRANSPOSED

__device__ __forceinline__ uint32_t smem_u32(const void* p) {
    uint32_t a;
    asm("{ .reg .u64 t; cvta.to.shared.u64 t, %1; cvt.u32.u64 %0, t; }" : "=r"(a) : "l"(p));
    return a;
}

// ---------------------------------------------------------------------------
// Kernel 1: fused QKV projection via bf16 mma.sync.
// CTA: 128 rows x 512 n (4 tiles of 128). Grid (8, 3, 16).
// rg0: rows = q(64)+k(64); rg1/rg2: v rows. A-frags (W) in registers.
// x chunks [64c x 128n] staged fp32->bf16, double-buffered, trans-ldmatrix B.
// ---------------------------------------------------------------------------
#define PW_STR 132                 // W row stride (words): 128 data + 4
#define PX_STR 68                  // x row stride (words): 64 data + 4
#define POW  0
#define POX0 (128 * PW_STR)        // 16896
#define POX1 (POX0 + 64 * PX_STR)  // 21248
#define PSMW (POX1 + 64 * PX_STR)  // 25600 words = 102400 B

__global__ __launch_bounds__(256, 1) void proj_kernel(
    const float* __restrict__ x,
    const float* __restrict__ Wq, const float* __restrict__ bq,
    const float* __restrict__ Wk, const float* __restrict__ bk,
    const float* __restrict__ Wv, const float* __restrict__ bv)
{
    extern __shared__ __align__(16) uint32_t psm[];
    const uint32_t smb = smem_u32(psm);

    const int t    = threadIdx.x;
    const int lane = t & 31;
    const int wid  = t >> 5;
    const int g    = lane >> 2;
    const int tg   = lane & 3;
    const int lrow = lane & 7;
    const int q8   = lane >> 3;
    const int rg   = blockIdx.y;
    const int b    = blockIdx.z;
    const int nbase = blockIdx.x * 512;

    // ---- stage W slice [128r x 256c] fp32 -> bf16 smem ----
    for (int f = t; f < 128 * 128; f += 256) {
        int r = f >> 7, cw = f & 127;
        const float* wrow;
        if (rg == 0) wrow = (r < 64) ? (Wq + r * CC) : (Wk + (r - 64) * CC);
        else         wrow = Wv + ((size_t)((rg - 1) * 128 + r)) * CC;
        float2 wv = *(const float2*)&wrow[cw * 2];
        uint32_t pk; PACK_BF16X2(pk, wv.x, wv.y);
        psm[r * PW_STR + cw] = pk;
    }
    __syncthreads();

    // ---- A fragments (W) in registers: 16 k16-steps x 4 ----
    uint32_t af[16][4];
    {
        const uint32_t abase = smb + 4 * ((wid * 16 + (q8 & 1) * 8 + lrow) * PW_STR + (q8 >> 1) * 4);
#pragma unroll
        for (int s = 0; s < 16; s++)
            LDSM_X4(af[s][0], af[s][1], af[s][2], af[s][3], abase + 4 * (s * 8));
    }

    // per-warp bias (rows wid*16+g, +8)
    const int row_g = wid * 16 + g;
    float bias_lo, bias_hi;
    if (rg == 0) {
        if (wid < 4) { bias_lo = bq[row_g]; bias_hi = bq[row_g + 8]; }
        else         { bias_lo = bk[row_g - 64]; bias_hi = bk[row_g - 56]; }
    } else {
        bias_lo = bv[(rg - 1) * 128 + row_g];
        bias_hi = bv[(rg - 1) * 128 + row_g + 8];
    }
    const float qscale = 1.4426950408889634f / 64.0f;

    // trans-ldmatrix lane base (within an x chunk): row = k-part, col = n-part
    const uint32_t xrowpart = ((q8 & 1) * 8 + lrow) * PX_STR * 4 + (q8 >> 1) * 16;

    // ---- prefetch tile 0 chunk 0 ----
    float4 pf[8];
#pragma unroll
    for (int i = 0; i < 8; i++)
        pf[i] = *(const float4*)&x[((size_t)b * CC + i * 8 + (t >> 5)) * NN + nbase + (t & 31) * 4];

    for (int tile = 0; tile < 4; tile++) {
        const int n0 = nbase + tile * 128;

        float acc[16][4];
#pragma unroll
        for (int nb = 0; nb < 16; nb++)
#pragma unroll
            for (int r = 0; r < 4; r++) acc[nb][r] = 0.f;

        for (int ck = 0; ck < 4; ck++) {
            __syncthreads();   // buffer (ck&1) free of all prior readers
            uint32_t* xb = psm + ((ck & 1) ? POX1 : POX0);
#pragma unroll
            for (int i = 0; i < 8; i++) {
                int c = i * 8 + (t >> 5);
                uint32_t w0, w1;
                PACK_BF16X2(w0, pf[i].x, pf[i].y);
                PACK_BF16X2(w1, pf[i].z, pf[i].w);
                *(uint2*)&xb[c * PX_STR + (t & 31) * 2] = make_uint2(w0, w1);
            }
            __syncthreads();

            // prefetch next chunk (or next tile's chunk 0)
            if (ck < 3) {
                int cb = (ck + 1) * 64;
#pragma unroll
                for (int i = 0; i < 8; i++)
                    pf[i] = *(const float4*)&x[((size_t)b * CC + cb + i * 8 + (t >> 5)) * NN + n0 + (t & 31) * 4];
            } else if (tile < 3) {
                int n0n = nbase + (tile + 1) * 128;
#pragma unroll
                for (int i = 0; i < 8; i++)
                    pf[i] = *(const float4*)&x[((size_t)b * CC + i * 8 + (t >> 5)) * NN + n0n + (t & 31) * 4];
            }

            // MMA: 4 k16-steps of this chunk
            const uint32_t xtbase = smb + 4 * ((ck & 1) ? POX1 : POX0) + xrowpart;
#pragma unroll
            for (int s = 0; s < 4; s++) {
                const int astep = ck * 4 + s;
#pragma unroll
                for (int nbp = 0; nbp < 8; nbp++) {
                    uint32_t b0, b1, b2, b3;
                    LDSM_T_X4(b0, b1, b2, b3, xtbase + s * 16 * PX_STR * 4 + nbp * 32);
                    MMA_BF16(acc[nbp*2][0], acc[nbp*2][1], acc[nbp*2][2], acc[nbp*2][3],
                             af[astep][0], af[astep][1], af[astep][2], af[astep][3], b0, b1);
                    MMA_BF16(acc[nbp*2+1][0], acc[nbp*2+1][1], acc[nbp*2+1][2], acc[nbp*2+1][3],
                             af[astep][0], af[astep][1], af[astep][2], af[astep][3], b2, b3);
                }
            }
        }

        // ---- epilogue ----
        if (rg != 0) {
            // V: direct bf16x2 stores to g_v[b][c][n]
            const int clo = (rg - 1) * 128 + wid * 16 + g;
#pragma unroll
            for (int nb = 0; nb < 16; nb++) {
                uint32_t w0, w1;
                PACK_BF16X2(w0, acc[nb][0] + bias_lo, acc[nb][1] + bias_lo);
                PACK_BF16X2(w1, acc[nb][2] + bias_hi, acc[nb][3] + bias_hi);
                *(uint32_t*)&g_v[((size_t)b * CC + clo) * NN + n0 + nb * 8 + 2 * tg] = w0;
                *(uint32_t*)&g_v[((size_t)b * CC + clo + 8) * NN + n0 + nb * 8 + 2 * tg] = w1;
            }
        } else {
            // q/k: bounce through smem for coalesced [n][a] writes
            __syncthreads();   // all warps done with x buffers
            uint32_t* dstbuf = psm + ((wid < 4) ? POX0 : POX1);
            const int rloc = (wid & 3) * 16 + g;
            const bool isq = (wid < 4);
            const float sc = isq ? qscale : 1.0f;
#pragma unroll
            for (int nb = 0; nb < 16; nb++) {
                uint32_t w0, w1;
                PACK_BF16X2(w0, (acc[nb][0] + bias_lo) * sc, (acc[nb][1] + bias_lo) * sc);
                PACK_BF16X2(w1, (acc[nb][2] + bias_hi) * sc, (acc[nb][3] + bias_hi) * sc);
                dstbuf[(rloc    ) * PX_STR + nb * 4 + tg] = w0;
                dstbuf[(rloc + 8) * PX_STR + nb * 4 + tg] = w1;
            }
            __syncthreads();
            // transposed write: thread -> one n column, 32 a-values, q then k
            const int nn = t & 127, half = t >> 7;
            const uint16_t* s16q = (const uint16_t*)(psm + POX0);
            const uint16_t* s16k = (const uint16_t*)(psm + POX1);
            uint32_t wout[16];
#pragma unroll
            for (int i = 0; i < 16; i++) {
                uint32_t lo = s16q[(half * 32 + 2 * i    ) * (PX_STR * 2) + nn];
                uint32_t hi = s16q[(half * 32 + 2 * i + 1) * (PX_STR * 2) + nn];
                wout[i] = lo | (hi << 16);
            }
            {
                uint4* p = (uint4*)&g_q[((size_t)b * NN + n0 + nn) * DA + half * 32];
                p[0] = make_uint4(wout[0], wout[1], wout[2], wout[3]);
                p[1] = make_uint4(wout[4], wout[5], wout[6], wout[7]);
                p[2] = make_uint4(wout[8], wout[9], wout[10], wout[11]);
                p[3] = make_uint4(wout[12], wout[13], wout[14], wout[15]);
            }
#pragma unroll
            for (int i = 0; i < 16; i++) {
                uint32_t lo = s16k[(half * 32 + 2 * i    ) * (PX_STR * 2) + nn];
                uint32_t hi = s16k[(half * 32 + 2 * i + 1) * (PX_STR * 2) + nn];
                wout[i] = lo | (hi << 16);
            }
            {
                uint4* p = (uint4*)&g_k[((size_t)b * NN + n0 + nn) * DA + half * 32];
                p[0] = make_uint4(wout[0], wout[1], wout[2], wout[3]);
                p[1] = make_uint4(wout[4], wout[5], wout[6], wout[7]);
                p[2] = make_uint4(wout[8], wout[9], wout[10], wout[11]);
                p[3] = make_uint4(wout[12], wout[13], wout[14], wout[15]);
            }
        }
    }
}

// ---------------------------------------------------------------------------
// Kernel 2: bf16 mma.sync flash attention (UNCHANGED from round 9).
// ---------------------------------------------------------------------------
#define STR 36
#define KW  (TJ * STR)
#define VW  (CC * STR)
#define OKS0 0
#define OVS0 KW
#define OKS1 (KW + VW)
#define OVS1 (2 * KW + VW)
#define SMW  (2 * (KW + VW))   // 92 KB

__global__ __launch_bounds__(256, 1) void attn_kernel(
    const float* __restrict__ x, float* __restrict__ out)
{
    extern __shared__ __align__(16) uint32_t sm[];
    const uint32_t smb = smem_u32(sm);

    const int t    = threadIdx.x;
    const int lane = t & 31;
    const int wid  = t >> 5;
    const int g    = lane >> 2;
    const int tg   = lane & 3;
    const int b    = blockIdx.y;
    const int i0   = blockIdx.x * TI;

    const int lrow = lane & 7;
    const int q8   = lane >> 3;
    const int bqr  = q8 >> 1, bqc = q8 & 1;
    const uint32_t rowpart = 4 * ((bqr * 8 + lrow) * STR + bqc * 4);

    uint32_t qa[4][4];
    {
        const __nv_bfloat16* qg = g_q + ((size_t)b * NN + i0 + wid * 16) * DA;
#pragma unroll
        for (int s = 0; s < 4; s++) {
            qa[s][0] = *(const uint32_t*)&qg[(size_t)(g    ) * DA + s * 16 + 2 * tg    ];
            qa[s][1] = *(const uint32_t*)&qg[(size_t)(g + 8) * DA + s * 16 + 2 * tg    ];
            qa[s][2] = *(const uint32_t*)&qg[(size_t)(g    ) * DA + s * 16 + 2 * tg + 8];
            qa[s][3] = *(const uint32_t*)&qg[(size_t)(g + 8) * DA + s * 16 + 2 * tg + 8];
        }
    }

    float o[32][4];
#pragma unroll
    for (int n = 0; n < 32; n++)
#pragma unroll
        for (int r = 0; r < 4; r++) o[n][r] = 0.f;

    float l0 = 0.f, l1 = 0.f;

    const __nv_bfloat16* kgb = g_k + (size_t)b * NN * DA;
    const __nv_bfloat16* vgb = g_v + (size_t)b * CC * NN;

    {
        uint32_t kdst = smb + OKS0 * 4;
#pragma unroll
        for (int f = t; f < 512; f += 256) {
            int r = f & 63, c4 = f >> 6;
            CP_ASYNC16(kdst + (r * STR + c4 * 4) * 4, kgb + (size_t)r * DA + c4 * 8);
        }
        uint32_t vdst = smb + OVS0 * 4;
#pragma unroll
        for (int f = t; f < 2048; f += 256) {
            int c = f & 255, c4 = f >> 8;
            CP_ASYNC16(vdst + (c * STR + c4 * 4) * 4, vgb + (size_t)c * NN + c4 * 8);
        }
        CP_COMMIT();
    }

    for (int jt = 0; jt < NN / TJ; jt++) {
        const int cur = jt & 1;
        __syncthreads();

        if (jt + 1 < NN / TJ) {
            const int j0n = (jt + 1) * TJ;
            const __nv_bfloat16* kg = kgb + (size_t)j0n * DA;
            uint32_t kdst = smb + (cur ? OKS0 : OKS1) * 4;
#pragma unroll
            for (int f = t; f < 512; f += 256) {
                int r = f & 63, c4 = f >> 6;
                CP_ASYNC16(kdst + (r * STR + c4 * 4) * 4, kg + (size_t)r * DA + c4 * 8);
            }
            const __nv_bfloat16* vg = vgb + j0n;
            uint32_t vdst = smb + (cur ? OVS0 : OVS1) * 4;
#pragma unroll
            for (int f = t; f < 2048; f += 256) {
                int c = f & 255, c4 = f >> 8;
                CP_ASYNC16(vdst + (c * STR + c4 * 4) * 4, vg + (size_t)c * NN + c4 * 8);
            }
            CP_COMMIT();
            CP_WAIT(1);
        } else {
            CP_WAIT(0);
        }
        __syncthreads();

        const uint32_t kbase = smb + (cur ? OKS1 : OKS0) * 4 + rowpart;
        const uint32_t vbase = smb + (cur ? OVS1 : OVS0) * 4 + rowpart;

        float sf[8][4];
#pragma unroll
        for (int n = 0; n < 8; n++)
#pragma unroll
            for (int r = 0; r < 4; r++) sf[n][r] = 0.f;
#pragma unroll
        for (int s = 0; s < 4; s++) {
#pragma unroll
            for (int nbp = 0; nbp < 4; nbp++) {
                uint32_t b0, b1, b2, b3;
                LDSM_X4(b0, b1, b2, b3, kbase + 4 * (nbp * 16 * STR + s * 8));
                MMA_BF16(sf[nbp*2][0], sf[nbp*2][1], sf[nbp*2][2], sf[nbp*2][3],
                         qa[s][0], qa[s][1], qa[s][2], qa[s][3], b0, b1);
                MMA_BF16(sf[nbp*2+1][0], sf[nbp*2+1][1], sf[nbp*2+1][2], sf[nbp*2+1][3],
                         qa[s][0], qa[s][1], qa[s][2], qa[s][3], b2, b3);
            }
        }

        uint32_t pa[4][4];
#pragma unroll
        for (int nb = 0; nb < 8; nb++) {
            float e0, e1, e2, e3;
            asm("ex2.approx.ftz.f32 %0, %1;" : "=f"(e0) : "f"(sf[nb][0]));
            asm("ex2.approx.ftz.f32 %0, %1;" : "=f"(e1) : "f"(sf[nb][1]));
            asm("ex2.approx.ftz.f32 %0, %1;" : "=f"(e2) : "f"(sf[nb][2]));
            asm("ex2.approx.ftz.f32 %0, %1;" : "=f"(e3) : "f"(sf[nb][3]));
            l0 += e0 + e1;
            l1 += e2 + e3;
            int s = nb >> 1, hi = (nb & 1) * 2;
            PACK_BF16X2(pa[s][hi    ], e0, e1);
            PACK_BF16X2(pa[s][hi + 1], e2, e3);
        }

#pragma unroll
        for (int s = 0; s < 4; s++) {
#pragma unroll
            for (int nbp = 0; nbp < 16; nbp++) {
                uint32_t b0, b1, b2, b3;
                LDSM_X4(b0, b1, b2, b3, vbase + 4 * (nbp * 16 * STR + s * 8));
                MMA_BF16(o[nbp*2][0], o[nbp*2][1], o[nbp*2][2], o[nbp*2][3],
                         pa[s][0], pa[s][1], pa[s][2], pa[s][3], b0, b1);
                MMA_BF16(o[nbp*2+1][0], o[nbp*2+1][1], o[nbp*2+1][2], o[nbp*2+1][3],
                         pa[s][0], pa[s][1], pa[s][2], pa[s][3], b2, b3);
            }
        }
    }

    l0 += __shfl_xor_sync(0xffffffffu, l0, 1);
    l0 += __shfl_xor_sync(0xffffffffu, l0, 2);
    l1 += __shfl_xor_sync(0xffffffffu, l1, 1);
    l1 += __shfl_xor_sync(0xffffffffu, l1, 2);
    const float linv0 = 1.0f / l0;
    const float linv1 = 1.0f / l1;

    const int r0 = i0 + wid * 16 + g;
#pragma unroll
    for (int nb = 0; nb < 32; nb++) {
        int c = nb * 8 + 2 * tg;
        size_t b0i = ((size_t)b * CC + c) * NN;
        size_t b1i = ((size_t)b * CC + c + 1) * NN;
        out[b0i + r0]     = fmaf(o[nb][0], linv0, x[b0i + r0]);
        out[b1i + r0]     = fmaf(o[nb][1], linv0, x[b1i + r0]);
        out[b0i + r0 + 8] = fmaf(o[nb][2], linv1, x[b0i + r0 + 8]);
        out[b1i + r0 + 8] = fmaf(o[nb][3], linv1, x[b1i + r0 + 8]);
    }
}

// ---------------------------------------------------------------------------
extern "C" void kernel_launch(void* const* d_in, const int* in_sizes, int n_in,
                              void* d_out, int out_size)
{
    const float* x  = (const float*)d_in[0];
    const float* Wq = (const float*)d_in[1];
    const float* bq = (const float*)d_in[2];
    const float* Wk = (const float*)d_in[3];
    const float* bk = (const float*)d_in[4];
    const float* Wv = (const float*)d_in[5];
    const float* bv = (const float*)d_in[6];
    float* out = (float*)d_out;

    cudaFuncSetAttribute(proj_kernel, cudaFuncAttributeMaxDynamicSharedMemorySize, PSMW * 4);
    cudaFuncSetAttribute(attn_kernel, cudaFuncAttributeMaxDynamicSharedMemorySize, SMW * 4);

    proj_kernel<<<dim3(8, 3, BB), 256, PSMW * 4>>>(x, Wq, bq, Wk, bk, Wv, bv);
    attn_kernel<<<dim3(NN / TI, BB), 256, SMW * 4>>>(x, out);
}

// round 11
// speedup vs baseline: 16.3744x; 1.2994x over previous
#include <cuda_runtime.h>
#include <cuda_bf16.h>
#include <cstdint>

#define BB 16
#define CC 256
#define NN 4096
#define DA 64
#define TI 128
#define TJ 128

typedef unsigned long long u64;

#define MMA_BF16(d0,d1,d2,d3,a0,a1,a2,a3,b0,b1) \
    asm volatile("mma.sync.aligned.m16n8k16.row.col.f32.bf16.bf16.f32 " \
        "{%0,%1,%2,%3}, {%4,%5,%6,%7}, {%8,%9}, {%0,%1,%2,%3};" \
        : "+f"(d0), "+f"(d1), "+f"(d2), "+f"(d3) \
        : "r"(a0), "r"(a1), "r"(a2), "r"(a3), "r"(b0), "r"(b1))

#define PACK_BF16X2(d, lo, hi) \
    asm("cvt.rn.bf16x2.f32 %0, %1, %2;" : "=r"(d) : "f"(hi), "f"(lo))

#define LDSM_X4(r0,r1,r2,r3, addr) \
    asm volatile("ldmatrix.sync.aligned.m8n8.x4.shared.b16 {%0,%1,%2,%3}, [%4];" \
        : "=r"(r0), "=r"(r1), "=r"(r2), "=r"(r3) : "r"(addr))

#define LDSM_T_X4(r0,r1,r2,r3, addr) \
    asm volatile("ldmatrix.sync.aligned.m8n8.x4.trans.shared.b16 {%0,%1,%2,%3}, [%4];" \
        : "=r"(r0), "=r"(r1), "=r"(r2), "=r"(r3) : "r"(addr))

// cp.async (sm_80+)
#define CP_ASYNC16(dst, src) \
    asm volatile("cp.async.cg.shared.global [%0], [%1], 16;" :: "r"(dst), "l"(src) : "memory")
#define CP_COMMIT() asm volatile("cp.async.commit_group;" ::: "memory")
#define CP_WAIT(n)  asm volatile("cp.async.wait_group %0;" :: "n"(n) : "memory")

// Scratch (bf16)
__device__ __nv_bfloat16 g_q[(size_t)BB * NN * DA];   // [b][n][a] (pre-scaled log2e/64)
__device__ __nv_bfloat16 g_k[(size_t)BB * NN * DA];   // [b][n][a]
__device__ __nv_bfloat16 g_v[(size_t)BB * CC * NN];   // [b][c][n] TRANSPOSED

__device__ __forceinline__ uint32_t smem_u32(const void* p) {
    uint32_t a;
    asm("{ .reg .u64 t; cvta.to.shared.u64 t, %1; cvt.u32.u64 %0, t; }" : "=r"(a) : "l"(p));
    return a;
}

// ---------------------------------------------------------------------------
// Kernel 1: fused QKV projection via bf16 mma.sync (UNCHANGED from round 10).
// ---------------------------------------------------------------------------
#define PW_STR 132
#define PX_STR 68
#define POW  0
#define POX0 (128 * PW_STR)
#define POX1 (POX0 + 64 * PX_STR)
#define PSMW (POX1 + 64 * PX_STR)

__global__ __launch_bounds__(256, 1) void proj_kernel(
    const float* __restrict__ x,
    const float* __restrict__ Wq, const float* __restrict__ bq,
    const float* __restrict__ Wk, const float* __restrict__ bk,
    const float* __restrict__ Wv, const float* __restrict__ bv)
{
    extern __shared__ __align__(16) uint32_t psm[];
    const uint32_t smb = smem_u32(psm);

    const int t    = threadIdx.x;
    const int lane = t & 31;
    const int wid  = t >> 5;
    const int g    = lane >> 2;
    const int tg   = lane & 3;
    const int lrow = lane & 7;
    const int q8   = lane >> 3;
    const int rg   = blockIdx.y;
    const int b    = blockIdx.z;
    const int nbase = blockIdx.x * 512;

    for (int f = t; f < 128 * 128; f += 256) {
        int r = f >> 7, cw = f & 127;
        const float* wrow;
        if (rg == 0) wrow = (r < 64) ? (Wq + r * CC) : (Wk + (r - 64) * CC);
        else         wrow = Wv + ((size_t)((rg - 1) * 128 + r)) * CC;
        float2 wv = *(const float2*)&wrow[cw * 2];
        uint32_t pk; PACK_BF16X2(pk, wv.x, wv.y);
        psm[r * PW_STR + cw] = pk;
    }
    __syncthreads();

    uint32_t af[16][4];
    {
        const uint32_t abase = smb + 4 * ((wid * 16 + (q8 & 1) * 8 + lrow) * PW_STR + (q8 >> 1) * 4);
#pragma unroll
        for (int s = 0; s < 16; s++)
            LDSM_X4(af[s][0], af[s][1], af[s][2], af[s][3], abase + 4 * (s * 8));
    }

    const int row_g = wid * 16 + g;
    float bias_lo, bias_hi;
    if (rg == 0) {
        if (wid < 4) { bias_lo = bq[row_g]; bias_hi = bq[row_g + 8]; }
        else         { bias_lo = bk[row_g - 64]; bias_hi = bk[row_g - 56]; }
    } else {
        bias_lo = bv[(rg - 1) * 128 + row_g];
        bias_hi = bv[(rg - 1) * 128 + row_g + 8];
    }
    const float qscale = 1.4426950408889634f / 64.0f;

    const uint32_t xrowpart = ((q8 & 1) * 8 + lrow) * PX_STR * 4 + (q8 >> 1) * 16;

    float4 pf[8];
#pragma unroll
    for (int i = 0; i < 8; i++)
        pf[i] = *(const float4*)&x[((size_t)b * CC + i * 8 + (t >> 5)) * NN + nbase + (t & 31) * 4];

    for (int tile = 0; tile < 4; tile++) {
        const int n0 = nbase + tile * 128;

        float acc[16][4];
#pragma unroll
        for (int nb = 0; nb < 16; nb++)
#pragma unroll
            for (int r = 0; r < 4; r++) acc[nb][r] = 0.f;

        for (int ck = 0; ck < 4; ck++) {
            __syncthreads();
            uint32_t* xb = psm + ((ck & 1) ? POX1 : POX0);
#pragma unroll
            for (int i = 0; i < 8; i++) {
                int c = i * 8 + (t >> 5);
                uint32_t w0, w1;
                PACK_BF16X2(w0, pf[i].x, pf[i].y);
                PACK_BF16X2(w1, pf[i].z, pf[i].w);
                *(uint2*)&xb[c * PX_STR + (t & 31) * 2] = make_uint2(w0, w1);
            }
            __syncthreads();

            if (ck < 3) {
                int cb = (ck + 1) * 64;
#pragma unroll
                for (int i = 0; i < 8; i++)
                    pf[i] = *(const float4*)&x[((size_t)b * CC + cb + i * 8 + (t >> 5)) * NN + n0 + (t & 31) * 4];
            } else if (tile < 3) {
                int n0n = nbase + (tile + 1) * 128;
#pragma unroll
                for (int i = 0; i < 8; i++)
                    pf[i] = *(const float4*)&x[((size_t)b * CC + i * 8 + (t >> 5)) * NN + n0n + (t & 31) * 4];
            }

            const uint32_t xtbase = smb + 4 * ((ck & 1) ? POX1 : POX0) + xrowpart;
#pragma unroll
            for (int s = 0; s < 4; s++) {
                const int astep = ck * 4 + s;
#pragma unroll
                for (int nbp = 0; nbp < 8; nbp++) {
                    uint32_t b0, b1, b2, b3;
                    LDSM_T_X4(b0, b1, b2, b3, xtbase + s * 16 * PX_STR * 4 + nbp * 32);
                    MMA_BF16(acc[nbp*2][0], acc[nbp*2][1], acc[nbp*2][2], acc[nbp*2][3],
                             af[astep][0], af[astep][1], af[astep][2], af[astep][3], b0, b1);
                    MMA_BF16(acc[nbp*2+1][0], acc[nbp*2+1][1], acc[nbp*2+1][2], acc[nbp*2+1][3],
                             af[astep][0], af[astep][1], af[astep][2], af[astep][3], b2, b3);
                }
            }
        }

        if (rg != 0) {
            const int clo = (rg - 1) * 128 + wid * 16 + g;
#pragma unroll
            for (int nb = 0; nb < 16; nb++) {
                uint32_t w0, w1;
                PACK_BF16X2(w0, acc[nb][0] + bias_lo, acc[nb][1] + bias_lo);
                PACK_BF16X2(w1, acc[nb][2] + bias_hi, acc[nb][3] + bias_hi);
                *(uint32_t*)&g_v[((size_t)b * CC + clo) * NN + n0 + nb * 8 + 2 * tg] = w0;
                *(uint32_t*)&g_v[((size_t)b * CC + clo + 8) * NN + n0 + nb * 8 + 2 * tg] = w1;
            }
        } else {
            __syncthreads();
            uint32_t* dstbuf = psm + ((wid < 4) ? POX0 : POX1);
            const int rloc = (wid & 3) * 16 + g;
            const bool isq = (wid < 4);
            const float sc = isq ? qscale : 1.0f;
#pragma unroll
            for (int nb = 0; nb < 16; nb++) {
                uint32_t w0, w1;
                PACK_BF16X2(w0, (acc[nb][0] + bias_lo) * sc, (acc[nb][1] + bias_lo) * sc);
                PACK_BF16X2(w1, (acc[nb][2] + bias_hi) * sc, (acc[nb][3] + bias_hi) * sc);
                dstbuf[(rloc    ) * PX_STR + nb * 4 + tg] = w0;
                dstbuf[(rloc + 8) * PX_STR + nb * 4 + tg] = w1;
            }
            __syncthreads();
            const int nn = t & 127, half = t >> 7;
            const uint16_t* s16q = (const uint16_t*)(psm + POX0);
            const uint16_t* s16k = (const uint16_t*)(psm + POX1);
            uint32_t wout[16];
#pragma unroll
            for (int i = 0; i < 16; i++) {
                uint32_t lo = s16q[(half * 32 + 2 * i    ) * (PX_STR * 2) + nn];
                uint32_t hi = s16q[(half * 32 + 2 * i + 1) * (PX_STR * 2) + nn];
                wout[i] = lo | (hi << 16);
            }
            {
                uint4* p = (uint4*)&g_q[((size_t)b * NN + n0 + nn) * DA + half * 32];
                p[0] = make_uint4(wout[0], wout[1], wout[2], wout[3]);
                p[1] = make_uint4(wout[4], wout[5], wout[6], wout[7]);
                p[2] = make_uint4(wout[8], wout[9], wout[10], wout[11]);
                p[3] = make_uint4(wout[12], wout[13], wout[14], wout[15]);
            }
#pragma unroll
            for (int i = 0; i < 16; i++) {
                uint32_t lo = s16k[(half * 32 + 2 * i    ) * (PX_STR * 2) + nn];
                uint32_t hi = s16k[(half * 32 + 2 * i + 1) * (PX_STR * 2) + nn];
                wout[i] = lo | (hi << 16);
            }
            {
                uint4* p = (uint4*)&g_k[((size_t)b * NN + n0 + nn) * DA + half * 32];
                p[0] = make_uint4(wout[0], wout[1], wout[2], wout[3]);
                p[1] = make_uint4(wout[4], wout[5], wout[6], wout[7]);
                p[2] = make_uint4(wout[8], wout[9], wout[10], wout[11]);
                p[3] = make_uint4(wout[12], wout[13], wout[14], wout[15]);
            }
        }
    }
}

// ---------------------------------------------------------------------------
// Kernel 2: bf16 mma.sync flash attention, TJ=128, j-half phase interleave.
// ---------------------------------------------------------------------------
#define KSTRW 36                  // K row stride (words): 32 data + 4
#define VSTRW 68                  // V row stride (words): 64 data + 4
#define KW  (TJ * KSTRW)          // 4608
#define VW  (CC * VSTRW)          // 17408
#define OKS0 0
#define OVS0 KW
#define OKS1 (KW + VW)
#define OVS1 (2 * KW + VW)
#define SMW  (2 * (KW + VW))      // 44032 words = 176128 B

__global__ __launch_bounds__(256, 1) void attn_kernel(
    const float* __restrict__ x, float* __restrict__ out)
{
    extern __shared__ __align__(16) uint32_t sm[];
    const uint32_t smb = smem_u32(sm);

    const int t    = threadIdx.x;
    const int lane = t & 31;
    const int wid  = t >> 5;       // 8 warps x 16 i-rows
    const int g    = lane >> 2;
    const int tg   = lane & 3;
    const int b    = blockIdx.y;
    const int i0   = blockIdx.x * TI;

    const int lrow = lane & 7;
    const int q8   = lane >> 3;
    const int bqr  = q8 >> 1, bqc = q8 & 1;
    const uint32_t krowpart = 4 * ((bqr * 8 + lrow) * KSTRW + bqc * 4);
    const uint32_t vrowpart = 4 * ((bqr * 8 + lrow) * VSTRW + bqc * 4);

    // ---- Q fragments in registers (4 k16-steps), loaded once ----
    uint32_t qa[4][4];
    {
        const __nv_bfloat16* qg = g_q + ((size_t)b * NN + i0 + wid * 16) * DA;
#pragma unroll
        for (int s = 0; s < 4; s++) {
            qa[s][0] = *(const uint32_t*)&qg[(size_t)(g    ) * DA + s * 16 + 2 * tg    ];
            qa[s][1] = *(const uint32_t*)&qg[(size_t)(g + 8) * DA + s * 16 + 2 * tg    ];
            qa[s][2] = *(const uint32_t*)&qg[(size_t)(g    ) * DA + s * 16 + 2 * tg + 8];
            qa[s][3] = *(const uint32_t*)&qg[(size_t)(g + 8) * DA + s * 16 + 2 * tg + 8];
        }
    }

    float o[32][4];
#pragma unroll
    for (int n = 0; n < 32; n++)
#pragma unroll
        for (int r = 0; r < 4; r++) o[n][r] = 0.f;

    float l0 = 0.f, l1 = 0.f;

    const __nv_bfloat16* kgb = g_k + (size_t)b * NN * DA;
    const __nv_bfloat16* vgb = g_v + (size_t)b * CC * NN;

    // ---- prologue: stage tile 0 into buffer 0 ----
    {
        uint32_t kdst = smb + OKS0 * 4;
#pragma unroll
        for (int f = t; f < 1024; f += 256) {
            int r = f >> 3, c4 = f & 7;
            CP_ASYNC16(kdst + (r * KSTRW + c4 * 4) * 4, kgb + (size_t)r * DA + c4 * 8);
        }
        uint32_t vdst = smb + OVS0 * 4;
#pragma unroll
        for (int f = t; f < 4096; f += 256) {
            int c = f >> 4, j4 = f & 15;
            CP_ASYNC16(vdst + (c * VSTRW + j4 * 4) * 4, vgb + (size_t)c * NN + j4 * 8);
        }
        CP_COMMIT();
    }

    for (int jt = 0; jt < NN / TJ; jt++) {
        const int cur = jt & 1;
        __syncthreads();   // all warps done reading the buffer to be overwritten

        if (jt + 1 < NN / TJ) {
            const int j0n = (jt + 1) * TJ;
            const __nv_bfloat16* kg = kgb + (size_t)j0n * DA;
            uint32_t kdst = smb + (cur ? OKS0 : OKS1) * 4;
#pragma unroll
            for (int f = t; f < 1024; f += 256) {
                int r = f >> 3, c4 = f & 7;
                CP_ASYNC16(kdst + (r * KSTRW + c4 * 4) * 4, kg + (size_t)r * DA + c4 * 8);
            }
            const __nv_bfloat16* vg = vgb + j0n;
            uint32_t vdst = smb + (cur ? OVS0 : OVS1) * 4;
#pragma unroll
            for (int f = t; f < 4096; f += 256) {
                int c = f >> 4, j4 = f & 15;
                CP_ASYNC16(vdst + (c * VSTRW + j4 * 4) * 4, vg + (size_t)c * NN + j4 * 8);
            }
            CP_COMMIT();
            CP_WAIT(1);
        } else {
            CP_WAIT(0);
        }
        __syncthreads();

        const uint32_t kbase = smb + (cur ? OKS1 : OKS0) * 4 + krowpart;
        const uint32_t vbase = smb + (cur ? OVS1 : OVS0) * 4 + vrowpart;

        // ======== j-half 0: S ========
        float sf[8][4];
#pragma unroll
        for (int n = 0; n < 8; n++)
#pragma unroll
            for (int r = 0; r < 4; r++) sf[n][r] = 0.f;
#pragma unroll
        for (int s = 0; s < 4; s++) {
#pragma unroll
            for (int nbp = 0; nbp < 4; nbp++) {
                uint32_t b0, b1, b2, b3;
                LDSM_X4(b0, b1, b2, b3, kbase + 4 * (nbp * 16 * KSTRW + s * 8));
                MMA_BF16(sf[nbp*2][0], sf[nbp*2][1], sf[nbp*2][2], sf[nbp*2][3],
                         qa[s][0], qa[s][1], qa[s][2], qa[s][3], b0, b1);
                MMA_BF16(sf[nbp*2+1][0], sf[nbp*2+1][1], sf[nbp*2+1][2], sf[nbp*2+1][3],
                         qa[s][0], qa[s][1], qa[s][2], qa[s][3], b2, b3);
            }
        }

        // ---- exp(h0) -> pa0 (overlaps S(h1) below: MUFU vs tensor) ----
        uint32_t pa0[4][4];
#pragma unroll
        for (int nb = 0; nb < 8; nb++) {
            float e0, e1, e2, e3;
            asm("ex2.approx.ftz.f32 %0, %1;" : "=f"(e0) : "f"(sf[nb][0]));
            asm("ex2.approx.ftz.f32 %0, %1;" : "=f"(e1) : "f"(sf[nb][1]));
            asm("ex2.approx.ftz.f32 %0, %1;" : "=f"(e2) : "f"(sf[nb][2]));
            asm("ex2.approx.ftz.f32 %0, %1;" : "=f"(e3) : "f"(sf[nb][3]));
            l0 += e0 + e1;
            l1 += e2 + e3;
            int s = nb >> 1, hi = (nb & 1) * 2;
            PACK_BF16X2(pa0[s][hi    ], e0, e1);
            PACK_BF16X2(pa0[s][hi + 1], e2, e3);
        }

        // ======== j-half 1: S (rows 64..127 of K tile) ========
#pragma unroll
        for (int n = 0; n < 8; n++)
#pragma unroll
            for (int r = 0; r < 4; r++) sf[n][r] = 0.f;
#pragma unroll
        for (int s = 0; s < 4; s++) {
#pragma unroll
            for (int nbp = 0; nbp < 4; nbp++) {
                uint32_t b0, b1, b2, b3;
                LDSM_X4(b0, b1, b2, b3, kbase + 4 * ((64 + nbp * 16) * KSTRW + s * 8));
                MMA_BF16(sf[nbp*2][0], sf[nbp*2][1], sf[nbp*2][2], sf[nbp*2][3],
                         qa[s][0], qa[s][1], qa[s][2], qa[s][3], b0, b1);
                MMA_BF16(sf[nbp*2+1][0], sf[nbp*2+1][1], sf[nbp*2+1][2], sf[nbp*2+1][3],
                         qa[s][0], qa[s][1], qa[s][2], qa[s][3], b2, b3);
            }
        }

        // ======== PV(h0): k-steps 0..3 with pa0 ========
#pragma unroll
        for (int s = 0; s < 4; s++) {
#pragma unroll
            for (int nbp = 0; nbp < 16; nbp++) {
                uint32_t b0, b1, b2, b3;
                LDSM_X4(b0, b1, b2, b3, vbase + 4 * (nbp * 16 * VSTRW + s * 8));
                MMA_BF16(o[nbp*2][0], o[nbp*2][1], o[nbp*2][2], o[nbp*2][3],
                         pa0[s][0], pa0[s][1], pa0[s][2], pa0[s][3], b0, b1);
                MMA_BF16(o[nbp*2+1][0], o[nbp*2+1][1], o[nbp*2+1][2], o[nbp*2+1][3],
                         pa0[s][0], pa0[s][1], pa0[s][2], pa0[s][3], b2, b3);
            }
        }

        // ---- exp(h1) -> pa1 (independent of PV(h0); compiler interleaves) ----
        uint32_t pa1[4][4];
#pragma unroll
        for (int nb = 0; nb < 8; nb++) {
            float e0, e1, e2, e3;
            asm("ex2.approx.ftz.f32 %0, %1;" : "=f"(e0) : "f"(sf[nb][0]));
            asm("ex2.approx.ftz.f32 %0, %1;" : "=f"(e1) : "f"(sf[nb][1]));
            asm("ex2.approx.ftz.f32 %0, %1;" : "=f"(e2) : "f"(sf[nb][2]));
            asm("ex2.approx.ftz.f32 %0, %1;" : "=f"(e3) : "f"(sf[nb][3]));
            l0 += e0 + e1;
            l1 += e2 + e3;
            int s = nb >> 1, hi = (nb & 1) * 2;
            PACK_BF16X2(pa1[s][hi    ], e0, e1);
            PACK_BF16X2(pa1[s][hi + 1], e2, e3);
        }

        // ======== PV(h1): k-steps 4..7 with pa1 ========
#pragma unroll
        for (int s = 0; s < 4; s++) {
#pragma unroll
            for (int nbp = 0; nbp < 16; nbp++) {
                uint32_t b0, b1, b2, b3;
                LDSM_X4(b0, b1, b2, b3, vbase + 4 * (nbp * 16 * VSTRW + (s + 4) * 8));
                MMA_BF16(o[nbp*2][0], o[nbp*2][1], o[nbp*2][2], o[nbp*2][3],
                         pa1[s][0], pa1[s][1], pa1[s][2], pa1[s][3], b0, b1);
                MMA_BF16(o[nbp*2+1][0], o[nbp*2+1][1], o[nbp*2+1][2], o[nbp*2+1][3],
                         pa1[s][0], pa1[s][1], pa1[s][2], pa1[s][3], b2, b3);
            }
        }
    }

    // ---- l complete within warp: quad reduce ----
    l0 += __shfl_xor_sync(0xffffffffu, l0, 1);
    l0 += __shfl_xor_sync(0xffffffffu, l0, 2);
    l1 += __shfl_xor_sync(0xffffffffu, l1, 1);
    l1 += __shfl_xor_sync(0xffffffffu, l1, 2);
    const float linv0 = 1.0f / l0;
    const float linv1 = 1.0f / l1;

    // ---- epilogue: out[b][c][i] = O/l + x ----
    const int r0 = i0 + wid * 16 + g;
#pragma unroll
    for (int nb = 0; nb < 32; nb++) {
        int c = nb * 8 + 2 * tg;
        size_t b0i = ((size_t)b * CC + c) * NN;
        size_t b1i = ((size_t)b * CC + c + 1) * NN;
        out[b0i + r0]     = fmaf(o[nb][0], linv0, x[b0i + r0]);
        out[b1i + r0]     = fmaf(o[nb][1], linv0, x[b1i + r0]);
        out[b0i + r0 + 8] = fmaf(o[nb][2], linv1, x[b0i + r0 + 8]);
        out[b1i + r0 + 8] = fmaf(o[nb][3], linv1, x[b1i + r0 + 8]);
    }
}

// ---------------------------------------------------------------------------
extern "C" void kernel_launch(void* const* d_in, const int* in_sizes, int n_in,
                              void* d_out, int out_size)
{
    const float* x  = (const float*)d_in[0];
    const float* Wq = (const float*)d_in[1];
    const float* bq = (const float*)d_in[2];
    const float* Wk = (const float*)d_in[3];
    const float* bk = (const float*)d_in[4];
    const float* Wv = (const float*)d_in[5];
    const float* bv = (const float*)d_in[6];
    float* out = (float*)d_out;

    cudaFuncSetAttribute(proj_kernel, cudaFuncAttributeMaxDynamicSharedMemorySize, PSMW * 4);
    cudaFuncSetAttribute(attn_kernel, cudaFuncAttributeMaxDynamicSharedMemorySize, SMW * 4);

    proj_kernel<<<dim3(8, 3, BB), 256, PSMW * 4>>>(x, Wq, bq, Wk, bk, Wv, bv);
    attn_kernel<<<dim3(NN / TI, BB), 256, SMW * 4>>>(x, out);
}